// round 13
// baseline (speedup 1.0000x reference)
#include <cuda_runtime.h>
#include <cuda_fp16.h>
#include <math.h>

// Problem constants
#define Bb   8
#define Tt   128
#define Nn   512
#define HIDc 4
#define Dd   2048
#define Ee   16384
#define FD   8192
#define NEG  0.2f

// k_lstm smem layout (dynamic, opt-in)
#define HROW   2056
#define NCACHE 22                     // k-chunks cached in smem (of 32)
#define NGLOB  (32 - NCACHE)
#define SM_HH    0
#define SM_FR    32896                // 8*2056*2
#define SM_CS    (SM_FR + 8192)
#define SM_WS    (SM_CS + 512)        // 41600, 16B aligned
#define SM_TOTAL (SM_WS + 16 * NCACHE * 32 * 16)   // + 176 KB = 221824

// ---------------- device scratch (no allocations allowed) ----------------
__device__ __align__(256) __half g_seq16[1024 * 2048];  // [T*B, D] GAT out fp16, 4 MB
__device__ __align__(256) float g_zxt[8192u * 1024u];   // Z^T [4D, T*B], 32 MB
__device__ __align__(256) unsigned g_wpk[8388608];      // w_hh packed A-frags, 32 MB
__device__ __align__(256) unsigned g_wpk2[8388608];     // w_ih packed A-frags, 32 MB
__device__ __align__(256) float  g_h[2][Bb * Dd];       // fp32 hidden (final linear)
__device__ __align__(256) __half g_h16[2][Bb * Dd];     // fp16 hidden (mma B operand)
__device__ __align__(256) int g_bar[128];               // per-BLOCK step flags (monotonic)
__device__ int   g_deg[Nn];
__device__ int   g_off[Nn];
__device__ int   g_csr[Ee];
__device__ float g_cs, g_cd;

// ---------------- helpers ----------------
typedef unsigned long long ull;

__device__ __forceinline__ ull pk2(float x, float y) {
    ull r;
    asm("mov.b64 %0, {%1, %2};" : "=l"(r) : "f"(x), "f"(y));
    return r;
}
__device__ __forceinline__ void ffma2(ull &d, ull a, ull b) {
    asm("fma.rn.f32x2 %0, %1, %2, %0;" : "+l"(d) : "l"(a), "l"(b));
}
__device__ __forceinline__ float fsum2(ull v) {
    float x, y;
    asm("mov.b64 {%0, %1}, %2;" : "=f"(x), "=f"(y) : "l"(v));
    return x + y;
}
__device__ __forceinline__ unsigned smem_u32(const void* p) {
    unsigned a;
    asm("{ .reg .u64 t; cvta.to.shared.u64 t, %1; cvt.u32.u64 %0, t; }"
        : "=r"(a) : "l"(p));
    return a;
}

// ---------------- weight packing: whh AND wih -> fp16 m16n8k16 A-frag order ----------------
__global__ void k_wcvt_all(const float* __restrict__ whh, const float* __restrict__ wih) {
    unsigned idx = blockIdx.x * 512 + threadIdx.x;
    if (idx < 2097152u) {
        unsigned lane  = idx & 31;
        unsigned ch    = (idx >> 5) & 31;
        unsigned outer = idx >> 10;
        unsigned ks  = outer & 3;
        unsigned mi  = (outer >> 2) & 3;
        unsigned bid = outer >> 4;
        unsigned rbase = mi * Dd + bid * 16 + (lane >> 2);
        unsigned kbase = ks * 512 + ch * 16 + (lane & 3) * 2;
        unsigned r[4];
#pragma unroll
        for (int rr = 0; rr < 4; rr++) {
            unsigned row = rbase + (rr & 1) * 8;
            unsigned k   = kbase + ((rr >> 1) & 1) * 8;
            float2 v = *(const float2*)(whh + (size_t)row * Dd + k);
            __half2 h = __floats2half2_rn(v.x, v.y);
            r[rr] = *reinterpret_cast<unsigned*>(&h);
        }
        ((uint4*)g_wpk)[idx] = make_uint4(r[0], r[1], r[2], r[3]);
    } else if (idx < 4194304u) {
        unsigned j = idx - 2097152u;
        unsigned lane = j & 31;
        unsigned kc   = (j >> 5) & 127;
        unsigned mt   = j >> 12;
        unsigned rbase = mt * 16 + (lane >> 2);
        unsigned kbase = kc * 16 + (lane & 3) * 2;
        unsigned r[4];
#pragma unroll
        for (int rr = 0; rr < 4; rr++) {
            unsigned row = rbase + (rr & 1) * 8;
            unsigned k   = kbase + ((rr >> 1) & 1) * 8;
            float2 v = *(const float2*)(wih + (size_t)row * Dd + k);
            __half2 h = __floats2half2_rn(v.x, v.y);
            r[rr] = *reinterpret_cast<unsigned*>(&h);
        }
        ((uint4*)g_wpk2)[j] = make_uint4(r[0], r[1], r[2], r[3]);
    }
}

// ---------------- fused CSR build: consts + degree + scan + fill (1 block) ----------------
__global__ void __launch_bounds__(512)
k_graph(const int* __restrict__ ei, const float* __restrict__ W,
        const float* __restrict__ as_, const float* __restrict__ ad_) {
    __shared__ int sdeg[Nn];
    __shared__ int s[Nn];
    __shared__ int scur[Nn];
    int tid = threadIdx.x;
    if (tid == 0) {
        float cs = 0.f, cd = 0.f;
        for (int k = 0; k < HIDc; k++) { cs += W[k] * as_[k]; cd += W[k] * ad_[k]; }
        g_cs = cs; g_cd = cd;
    }
    sdeg[tid] = 0;
    if (tid < 128) g_bar[tid] = 0;     // clear per-block step flags each call
    __syncthreads();
    for (int e = tid; e < Ee; e += 512) atomicAdd(&sdeg[ei[Ee + e]], 1);
    __syncthreads();
    int d = sdeg[tid];
    s[tid] = d;
    __syncthreads();
    for (int off = 1; off < Nn; off <<= 1) {
        int t = 0;
        if (tid >= off) t = s[tid - off];
        __syncthreads();
        s[tid] += t;
        __syncthreads();
    }
    g_deg[tid] = d;
    g_off[tid] = s[tid] - d;
    scur[tid] = s[tid] - d;
    __syncthreads();
    for (int e = tid; e < Ee; e += 512) {
        int src = ei[e];
        int dst = ei[Ee + e];
        int pos = atomicAdd(&scur[dst], 1);
        g_csr[pos] = src;
    }
}

// GAT for batch-0 nodes. One block per t. Writes fp16.
__global__ void k_gat_b0(const float* __restrict__ x, const float* __restrict__ W,
                         const float* __restrict__ bias) {
    __shared__ float xs[Nn];
    int t = blockIdx.x;
    int i = threadIdx.x;
    xs[i] = x[t * Nn + i];
    __syncthreads();
    float cs = g_cs, cd = g_cd;
    float xi = xs[i];
    float es = xi * (cs + cd);
    es = es > 0.f ? es : NEG * es;
    int beg = g_off[i], end = beg + g_deg[i];
    float m = es;
    for (int e = beg; e < end; e++) {
        float v = cs * xs[g_csr[e]] + cd * xi;
        v = v > 0.f ? v : NEG * v;
        m = fmaxf(m, v);
    }
    float den = expf(es - m);
    float ssum = den * xi;
    for (int e = beg; e < end; e++) {
        float xsrc = xs[g_csr[e]];
        float v = cs * xsrc + cd * xi;
        v = v > 0.f ? v : NEG * v;
        float w = expf(v - m);
        den += w;
        ssum += w * xsrc;
    }
    float sA = ssum / den;
    float gg[4];
#pragma unroll
    for (int k = 0; k < HIDc; k++) {
        float g = fmaf(sA, W[k], bias[k]);
        gg[k] = g > 0.f ? g : 0.f;
    }
    __half2 a = __floats2half2_rn(gg[0], gg[1]);
    __half2 b = __floats2half2_rn(gg[2], gg[3]);
    *(uint2*)(&g_seq16[(size_t)(t * Bb) * Dd + i * HIDc]) =
        make_uint2(*reinterpret_cast<unsigned*>(&a), *reinterpret_cast<unsigned*>(&b));
}

// GAT for batches 1..7: self-loop only => s = x. Writes fp16.
__global__ void k_gat_rest(const float* __restrict__ x, const float* __restrict__ W,
                           const float* __restrict__ bias) {
    int idx = blockIdx.x * 256 + threadIdx.x;
    if (idx >= Tt * (Bb - 1) * Nn) return;
    int t = idx / ((Bb - 1) * Nn);
    int r = idx - t * (Bb - 1) * Nn;
    int b = 1 + (r >> 9);
    int n = r & (Nn - 1);
    float xi = x[((size_t)b * Tt + t) * Nn + n];
    float gg[4];
#pragma unroll
    for (int k = 0; k < HIDc; k++) {
        float g = fmaf(xi, W[k], bias[k]);
        gg[k] = g > 0.f ? g : 0.f;
    }
    __half2 a = __floats2half2_rn(gg[0], gg[1]);
    __half2 bh = __floats2half2_rn(gg[2], gg[3]);
    *(uint2*)(&g_seq16[(size_t)(t * Bb + b) * Dd + n * HIDc]) =
        make_uint2(*reinterpret_cast<unsigned*>(&a), *reinterpret_cast<unsigned*>(&bh));
}

// ---------------- input GEMM on HMMA: Z^T[8192,1024] = w_ih @ seq^T + bias ----------------
#define BROW 40
__global__ void __launch_bounds__(512, 1)
k_zxt(const float* __restrict__ bih, const float* __restrict__ bhh) {
    __shared__ __align__(16) __half Bs[2][256 * BROW];
    int tid = threadIdx.x;
    int wi = tid >> 5;
    int lane = tid & 31;
    int wm = wi >> 2;
    int wn = wi & 3;
    int bm = blockIdx.y * 128;
    int bn = blockIdx.x * 256;

    int li0 = tid * 2;
    int row0 = li0 >> 2, c0 = li0 & 3;
    int li1 = li0 + 1;
    int row1 = li1 >> 2, c1 = li1 & 3;
    const __half* src0 = g_seq16 + (size_t)(bn + row0) * Dd + c0 * 8;
    const __half* src1 = g_seq16 + (size_t)(bn + row1) * Dd + c1 * 8;
    unsigned dst0 = smem_u32(&Bs[0][row0 * BROW + c0 * 8]);
    unsigned dst1 = smem_u32(&Bs[0][row1 * BROW + c1 * 8]);
    const unsigned bufB = 256 * BROW * 2;

    const uint4* Ap = ((const uint4*)g_wpk2) + ((size_t)(bm / 16 + wm * 2) * 128) * 32 + lane;
    int bfrag = (wn * 64 + (lane >> 2)) * BROW + (lane & 3) * 2;

    float acc[2][8][4];
#pragma unroll
    for (int a = 0; a < 2; a++)
#pragma unroll
        for (int b = 0; b < 8; b++)
#pragma unroll
            for (int c = 0; c < 4; c++) acc[a][b][c] = 0.f;

    asm volatile("cp.async.cg.shared.global [%0], [%1], 16;" :: "r"(dst0), "l"(src0));
    asm volatile("cp.async.cg.shared.global [%0], [%1], 16;" :: "r"(dst1), "l"(src1));
    asm volatile("cp.async.commit_group;");

    for (int kt = 0; kt < 64; kt++) {
        int buf = kt & 1;
        if (kt + 1 < 64) {
            unsigned off = ((kt + 1) & 1) * bufB;
            asm volatile("cp.async.cg.shared.global [%0], [%1], 16;"
                         :: "r"(dst0 + off), "l"(src0 + (kt + 1) * 32));
            asm volatile("cp.async.cg.shared.global [%0], [%1], 16;"
                         :: "r"(dst1 + off), "l"(src1 + (kt + 1) * 32));
            asm volatile("cp.async.commit_group;");
            asm volatile("cp.async.wait_group 1;");
        } else {
            asm volatile("cp.async.wait_group 0;");
        }
        __syncthreads();

        const __half* Bb_ = &Bs[buf][bfrag];
#pragma unroll
        for (int kk = 0; kk < 2; kk++) {
            int kc = kt * 2 + kk;
            uint4 a0 = Ap[(size_t)(0 * 128 + kc) * 32];
            uint4 a1 = Ap[(size_t)(1 * 128 + kc) * 32];
#pragma unroll
            for (int nt = 0; nt < 8; nt++) {
                unsigned b0 = *(const unsigned*)(Bb_ + nt * 8 * BROW + kk * 16);
                unsigned b1 = *(const unsigned*)(Bb_ + nt * 8 * BROW + kk * 16 + 8);
                asm volatile(
                    "mma.sync.aligned.m16n8k16.row.col.f32.f16.f16.f32 "
                    "{%0,%1,%2,%3}, {%4,%5,%6,%7}, {%8,%9}, {%0,%1,%2,%3};"
                    : "+f"(acc[0][nt][0]), "+f"(acc[0][nt][1]),
                      "+f"(acc[0][nt][2]), "+f"(acc[0][nt][3])
                    : "r"(a0.x), "r"(a0.y), "r"(a0.z), "r"(a0.w), "r"(b0), "r"(b1));
                asm volatile(
                    "mma.sync.aligned.m16n8k16.row.col.f32.f16.f16.f32 "
                    "{%0,%1,%2,%3}, {%4,%5,%6,%7}, {%8,%9}, {%0,%1,%2,%3};"
                    : "+f"(acc[1][nt][0]), "+f"(acc[1][nt][1]),
                      "+f"(acc[1][nt][2]), "+f"(acc[1][nt][3])
                    : "r"(a1.x), "r"(a1.y), "r"(a1.z), "r"(a1.w), "r"(b0), "r"(b1));
            }
        }
        __syncthreads();
    }

#pragma unroll
    for (int mtl = 0; mtl < 2; mtl++) {
        int m = bm + wm * 32 + mtl * 16 + (lane >> 2);
        float bA = bih[m] + bhh[m];
        float bB = bih[m + 8] + bhh[m + 8];
#pragma unroll
        for (int nt = 0; nt < 8; nt++) {
            int n = bn + wn * 64 + nt * 8 + (lane & 3) * 2;
            *(float2*)(&g_zxt[(size_t)m * 1024 + n]) =
                make_float2(acc[mtl][nt][0] + bA, acc[mtl][nt][1] + bA);
            *(float2*)(&g_zxt[(size_t)(m + 8) * 1024 + n]) =
                make_float2(acc[mtl][nt][2] + bB, acc[mtl][nt][3] + bB);
        }
    }
}

// ---------------- persistent LSTM: flag barrier + split mma chains ----------------
__global__ void __launch_bounds__(512, 1)
k_lstm(const float* __restrict__ wlin, const float* __restrict__ blin,
       float* __restrict__ out) {
    extern __shared__ __align__(16) char smem[];
    __half* h_h = (__half*)(smem + SM_HH);
    float*  fr  = (float*)(smem + SM_FR);
    float*  cs_ = (float*)(smem + SM_CS);
    uint4*  ws  = (uint4*)(smem + SM_WS);

    int tid = threadIdx.x;
    int wi = tid >> 5;
    int lane = tid & 31;
    int bid = blockIdx.x;
    int d0 = bid * 16;
    int ks = wi & 3;
    int mi = wi >> 2;
    const uint4* Abase = ((const uint4*)g_wpk) + ((size_t)(bid * 16 + mi * 4 + ks) * 32) * 32;
    int k0base = ks * 512;
    const __half* hb = &h_h[(lane >> 2) * HROW];
    uint4* wsw = ws + wi * (NCACHE * 32);

    int dd2 = tid >> 3;
    int bb = tid & 7;
    const float* zxb = g_zxt + (size_t)(d0 + dd2) * 1024 + bb;

    // preload weight cache, zero h, zero c
#pragma unroll
    for (int ch = 0; ch < NCACHE; ch++)
        wsw[ch * 32 + lane] = Abase[ch * 32 + lane];
    for (int u = tid; u < Bb * HROW / 8; u += 512)
        ((uint4*)h_h)[u] = make_uint4(0, 0, 0, 0);
    if (tid < 128) cs_[tid] = 0.f;
    __syncthreads();

    for (int t = 0; t < Tt; t++) {
        float zpre[4];
        if (tid < 128) {
            const float* zp = zxb + t * Bb;
#pragma unroll
            for (int g4 = 0; g4 < 4; g4++) zpre[g4] = zp[(size_t)g4 * 2097152];
        }

        if (t > 0) {
            const __half* hin = g_h16[t & 1];
#pragma unroll
            for (int u = 0; u < 4; u++) {
                int i = tid + u * 512;
                int b = i >> 8, k8 = i & 255;
                uint4 v = *(const uint4*)(hin + ((size_t)b << 11) + k8 * 8);
                *(uint4*)(&h_h[b * HROW + k8 * 8]) = v;
            }
            __syncthreads();
        }

        // 4 independent accumulator chains (8 mmas each) to break the RAW chain
        float a4[4][4];
#pragma unroll
        for (int cc = 0; cc < 4; cc++)
#pragma unroll
            for (int j = 0; j < 4; j++) a4[cc][j] = 0.f;

#pragma unroll
        for (int q = 0; q < 32; q++) {
            int ch = (q < NGLOB) ? (NCACHE + q) : (q - NGLOB);
            uint4 a = (q < NGLOB) ? Abase[ch * 32 + lane] : wsw[ch * 32 + lane];
            int k = k0base + ch * 16 + (lane & 3) * 2;
            unsigned b0 = *(const unsigned*)(hb + k);
            unsigned b1 = *(const unsigned*)(hb + k + 8);
            float* c = a4[q & 3];
            asm volatile(
                "mma.sync.aligned.m16n8k16.row.col.f32.f16.f16.f32 "
                "{%0,%1,%2,%3}, {%4,%5,%6,%7}, {%8,%9}, {%0,%1,%2,%3};"
                : "+f"(c[0]), "+f"(c[1]), "+f"(c[2]), "+f"(c[3])
                : "r"(a.x), "r"(a.y), "r"(a.z), "r"(a.w), "r"(b0), "r"(b1));
        }
        float c0 = (a4[0][0] + a4[1][0]) + (a4[2][0] + a4[3][0]);
        float c1 = (a4[0][1] + a4[1][1]) + (a4[2][1] + a4[3][1]);
        float c2 = (a4[0][2] + a4[1][2]) + (a4[2][2] + a4[3][2]);
        float c3 = (a4[0][3] + a4[1][3]) + (a4[2][3] + a4[3][3]);
        *(float4*)(&fr[((ks * 4 + mi) * 32 + lane) * 4]) = make_float4(c0, c1, c2, c3);
        __syncthreads();

        if (tid < 128) {
            int li = (dd2 & 7) * 4 + (bb >> 1);
            int ri = (bb & 1) + ((dd2 >> 3) << 1);
            float z[4];
#pragma unroll
            for (int g4 = 0; g4 < 4; g4++) {
                float s = zpre[g4];
#pragma unroll
                for (int kss = 0; kss < 4; kss++)
                    s += fr[((kss * 4 + g4) * 32 + li) * 4 + ri];
                z[g4] = s;
            }
            float ig = 1.f / (1.f + expf(-z[0]));
            float fg = 1.f / (1.f + expf(-z[1]));
            float gg = tanhf(z[2]);
            float og = 1.f / (1.f + expf(-z[3]));
            float cn = fg * cs_[bb * 16 + dd2] + ig * gg;
            cs_[bb * 16 + dd2] = cn;
            float hn = og * tanhf(cn);
            int par = (t + 1) & 1;
            g_h16[par][bb * Dd + d0 + dd2] = __float2half(hn);
            g_h[par][bb * Dd + d0 + dd2] = hn;
        }
        __syncthreads();   // all h writes done before release

        // flag barrier: per-block monotonic flags, no atomic contention
        if (tid == 0) {
            asm volatile("st.release.gpu.u32 [%0], %1;"
                         :: "l"(&g_bar[bid]), "r"(t + 1) : "memory");
        }
        if (wi == 0) {
            const int* f = g_bar + lane * 4;
            bool ok;
            do {
                int v0, v1, v2, v3;
                asm volatile("ld.acquire.gpu.u32 %0, [%1];" : "=r"(v0) : "l"(f) : "memory");
                asm volatile("ld.acquire.gpu.u32 %0, [%1];" : "=r"(v1) : "l"(f + 1) : "memory");
                asm volatile("ld.acquire.gpu.u32 %0, [%1];" : "=r"(v2) : "l"(f + 2) : "memory");
                asm volatile("ld.acquire.gpu.u32 %0, [%1];" : "=r"(v3) : "l"(f + 3) : "memory");
                ok = (v0 > t) && (v1 > t) && (v2 > t) && (v3 > t);
            } while (!__all_sync(0xffffffffu, ok));
        }
        __syncthreads();
    }

    // final linear: h_T in g_h[0]
    {
        int col = bid * 4 + (wi & 3);
        int p = wi >> 2;
        const float* wl = wlin + (size_t)col * Dd + lane * 4;
        const float* h0 = g_h[0] + (size_t)(2 * p) * Dd + lane * 4;
        const float* h1 = g_h[0] + (size_t)(2 * p + 1) * Dd + lane * 4;
        ull s0 = 0ull, s1 = 0ull;
#pragma unroll 4
        for (int it = 0; it < 16; it++) {
            int ko = it * 128;
            ulonglong2 wv = *(const ulonglong2*)(wl + ko);
            ulonglong2 hv0 = *(const ulonglong2*)(h0 + ko);
            ulonglong2 hv1 = *(const ulonglong2*)(h1 + ko);
            ffma2(s0, wv.x, hv0.x);
            ffma2(s0, wv.y, hv0.y);
            ffma2(s1, wv.x, hv1.x);
            ffma2(s1, wv.y, hv1.y);
        }
        float f0 = fsum2(s0), f1 = fsum2(s1);
#pragma unroll
        for (int d = 16; d; d >>= 1) {
            f0 += __shfl_xor_sync(0xffffffffu, f0, d);
            f1 += __shfl_xor_sync(0xffffffffu, f1, d);
        }
        if (lane == 0) {
            float bl = blin[col];
            out[(2 * p) * Nn + col]     = f0 + bl;
            out[(2 * p + 1) * Nn + col] = f1 + bl;
        }
    }
}

// ---------------- launch ----------------
extern "C" void kernel_launch(void* const* d_in, const int* in_sizes, int n_in,
                              void* d_out, int out_size) {
    const float* x    = (const float*)d_in[0];
    const float* gw   = (const float*)d_in[1];
    const float* as_  = (const float*)d_in[2];
    const float* ad_  = (const float*)d_in[3];
    const float* gb   = (const float*)d_in[4];
    const float* wih  = (const float*)d_in[5];
    const float* whh  = (const float*)d_in[6];
    const float* bih  = (const float*)d_in[7];
    const float* bhh  = (const float*)d_in[8];
    const float* wlin = (const float*)d_in[9];
    const float* blin = (const float*)d_in[10];
    const int*   ei   = (const int*)d_in[11];
    (void)in_sizes; (void)n_in; (void)out_size;

    static int smem_set = 0;
    if (!smem_set) {
        cudaFuncSetAttribute(k_lstm, cudaFuncAttributeMaxDynamicSharedMemorySize, SM_TOTAL);
        smem_set = 1;
    }

    // pack both weight matrices (one launch)
    k_wcvt_all<<<8192, 512>>>(whh, wih);

    // fused CSR build + consts + flag clear (one block)
    k_graph<<<1, 512>>>(ei, gw, as_, ad_);

    // GAT -> g_seq16 [1024, 2048] fp16
    k_gat_b0<<<Tt, Nn>>>(x, gw, gb);
    k_gat_rest<<<1792, 256>>>(x, gw, gb);

    // Input projection (HMMA): Z^T = w_ih @ seq^T + bias
    {
        dim3 grid(4, 64);
        k_zxt<<<grid, 512>>>(bih, bhh);
    }

    // Persistent LSTM (flag barrier) + final linear
    k_lstm<<<128, 512, SM_TOTAL>>>(wlin, blin, (float*)d_out);
}

// round 14
// speedup vs baseline: 2.1210x; 2.1210x over previous
#include <cuda_runtime.h>
#include <cuda_fp16.h>
#include <math.h>

// Problem constants
#define Bb   8
#define Tt   128
#define Nn   512
#define HIDc 4
#define Dd   2048
#define Ee   16384
#define FD   8192
#define NEG  0.2f

// k_lstm smem layout (dynamic, opt-in)
#define HROW   2056
#define NCACHE 22                     // k-chunks cached in smem (of 32)
#define NGLOB  (32 - NCACHE)
#define SM_HH    0
#define SM_FR    32896                // 8*2056*2
#define SM_CS    (SM_FR + 8192)
#define SM_WS    (SM_CS + 512)        // 41600, 16B aligned
#define SM_TOTAL (SM_WS + 16 * NCACHE * 32 * 16)   // + 176 KB = 221824

// ---------------- device scratch (no allocations allowed) ----------------
__device__ __align__(256) __half g_seq16[1024 * 2048];  // [T*B, D] GAT out fp16, 4 MB
__device__ __align__(256) float g_zxt[8192u * 1024u];   // Z^T [4D, T*B], 32 MB
__device__ __align__(256) unsigned g_wpk[8388608];      // w_hh packed A-frags, 32 MB
__device__ __align__(256) unsigned g_wpk2[8388608];     // w_ih packed A-frags, 32 MB
__device__ __align__(256) float  g_h[2][Bb * Dd];       // fp32 hidden (final linear)
__device__ __align__(256) __half g_h16[2][Bb * Dd];     // fp16 hidden (mma B operand)
__device__ int   g_bar[Tt];
__device__ int   g_deg[Nn];
__device__ int   g_off[Nn];
__device__ int   g_csr[Ee];
__device__ float g_cs, g_cd;

// ---------------- helpers ----------------
typedef unsigned long long ull;

__device__ __forceinline__ ull pk2(float x, float y) {
    ull r;
    asm("mov.b64 %0, {%1, %2};" : "=l"(r) : "f"(x), "f"(y));
    return r;
}
__device__ __forceinline__ void ffma2(ull &d, ull a, ull b) {
    asm("fma.rn.f32x2 %0, %1, %2, %0;" : "+l"(d) : "l"(a), "l"(b));
}
__device__ __forceinline__ float fsum2(ull v) {
    float x, y;
    asm("mov.b64 {%0, %1}, %2;" : "=f"(x), "=f"(y) : "l"(v));
    return x + y;
}
__device__ __forceinline__ unsigned smem_u32(const void* p) {
    unsigned a;
    asm("{ .reg .u64 t; cvta.to.shared.u64 t, %1; cvt.u32.u64 %0, t; }"
        : "=r"(a) : "l"(p));
    return a;
}

// ---------------- weight packing: whh AND wih -> fp16 m16n8k16 A-frag order ----------------
__global__ void k_wcvt_all(const float* __restrict__ whh, const float* __restrict__ wih) {
    unsigned idx = blockIdx.x * 512 + threadIdx.x;
    if (idx < 2097152u) {
        unsigned lane  = idx & 31;
        unsigned ch    = (idx >> 5) & 31;
        unsigned outer = idx >> 10;
        unsigned ks  = outer & 3;
        unsigned mi  = (outer >> 2) & 3;
        unsigned bid = outer >> 4;
        unsigned rbase = mi * Dd + bid * 16 + (lane >> 2);
        unsigned kbase = ks * 512 + ch * 16 + (lane & 3) * 2;
        unsigned r[4];
#pragma unroll
        for (int rr = 0; rr < 4; rr++) {
            unsigned row = rbase + (rr & 1) * 8;
            unsigned k   = kbase + ((rr >> 1) & 1) * 8;
            float2 v = *(const float2*)(whh + (size_t)row * Dd + k);
            __half2 h = __floats2half2_rn(v.x, v.y);
            r[rr] = *reinterpret_cast<unsigned*>(&h);
        }
        ((uint4*)g_wpk)[idx] = make_uint4(r[0], r[1], r[2], r[3]);
    } else if (idx < 4194304u) {
        unsigned j = idx - 2097152u;
        unsigned lane = j & 31;
        unsigned kc   = (j >> 5) & 127;
        unsigned mt   = j >> 12;
        unsigned rbase = mt * 16 + (lane >> 2);
        unsigned kbase = kc * 16 + (lane & 3) * 2;
        unsigned r[4];
#pragma unroll
        for (int rr = 0; rr < 4; rr++) {
            unsigned row = rbase + (rr & 1) * 8;
            unsigned k   = kbase + ((rr >> 1) & 1) * 8;
            float2 v = *(const float2*)(wih + (size_t)row * Dd + k);
            __half2 h = __floats2half2_rn(v.x, v.y);
            r[rr] = *reinterpret_cast<unsigned*>(&h);
        }
        ((uint4*)g_wpk2)[j] = make_uint4(r[0], r[1], r[2], r[3]);
    }
}

// ---------------- fused CSR build: consts + degree + scan + fill (1 block) ----------------
__global__ void __launch_bounds__(512)
k_graph(const int* __restrict__ ei, const float* __restrict__ W,
        const float* __restrict__ as_, const float* __restrict__ ad_) {
    __shared__ int sdeg[Nn];
    __shared__ int s[Nn];
    __shared__ int scur[Nn];
    int tid = threadIdx.x;
    if (tid == 0) {
        float cs = 0.f, cd = 0.f;
        for (int k = 0; k < HIDc; k++) { cs += W[k] * as_[k]; cd += W[k] * ad_[k]; }
        g_cs = cs; g_cd = cd;
    }
    sdeg[tid] = 0;
    if (tid < Tt) g_bar[tid] = 0;
    __syncthreads();
    for (int e = tid; e < Ee; e += 512) atomicAdd(&sdeg[ei[Ee + e]], 1);
    __syncthreads();
    int d = sdeg[tid];
    s[tid] = d;
    __syncthreads();
    for (int off = 1; off < Nn; off <<= 1) {
        int t = 0;
        if (tid >= off) t = s[tid - off];
        __syncthreads();
        s[tid] += t;
        __syncthreads();
    }
    g_deg[tid] = d;
    g_off[tid] = s[tid] - d;
    scur[tid] = s[tid] - d;
    __syncthreads();
    for (int e = tid; e < Ee; e += 512) {
        int src = ei[e];
        int dst = ei[Ee + e];
        int pos = atomicAdd(&scur[dst], 1);
        g_csr[pos] = src;
    }
}

// GAT for batch-0 nodes. One block per t. Writes fp16.
__global__ void k_gat_b0(const float* __restrict__ x, const float* __restrict__ W,
                         const float* __restrict__ bias) {
    __shared__ float xs[Nn];
    int t = blockIdx.x;
    int i = threadIdx.x;
    xs[i] = x[t * Nn + i];
    __syncthreads();
    float cs = g_cs, cd = g_cd;
    float xi = xs[i];
    float es = xi * (cs + cd);
    es = es > 0.f ? es : NEG * es;
    int beg = g_off[i], end = beg + g_deg[i];
    float m = es;
    for (int e = beg; e < end; e++) {
        float v = cs * xs[g_csr[e]] + cd * xi;
        v = v > 0.f ? v : NEG * v;
        m = fmaxf(m, v);
    }
    float den = expf(es - m);
    float ssum = den * xi;
    for (int e = beg; e < end; e++) {
        float xsrc = xs[g_csr[e]];
        float v = cs * xsrc + cd * xi;
        v = v > 0.f ? v : NEG * v;
        float w = expf(v - m);
        den += w;
        ssum += w * xsrc;
    }
    float sA = ssum / den;
    float gg[4];
#pragma unroll
    for (int k = 0; k < HIDc; k++) {
        float g = fmaf(sA, W[k], bias[k]);
        gg[k] = g > 0.f ? g : 0.f;
    }
    __half2 a = __floats2half2_rn(gg[0], gg[1]);
    __half2 b = __floats2half2_rn(gg[2], gg[3]);
    *(uint2*)(&g_seq16[(size_t)(t * Bb) * Dd + i * HIDc]) =
        make_uint2(*reinterpret_cast<unsigned*>(&a), *reinterpret_cast<unsigned*>(&b));
}

// GAT for batches 1..7: self-loop only => s = x. Writes fp16.
__global__ void k_gat_rest(const float* __restrict__ x, const float* __restrict__ W,
                           const float* __restrict__ bias) {
    int idx = blockIdx.x * 256 + threadIdx.x;
    if (idx >= Tt * (Bb - 1) * Nn) return;
    int t = idx / ((Bb - 1) * Nn);
    int r = idx - t * (Bb - 1) * Nn;
    int b = 1 + (r >> 9);
    int n = r & (Nn - 1);
    float xi = x[((size_t)b * Tt + t) * Nn + n];
    float gg[4];
#pragma unroll
    for (int k = 0; k < HIDc; k++) {
        float g = fmaf(xi, W[k], bias[k]);
        gg[k] = g > 0.f ? g : 0.f;
    }
    __half2 a = __floats2half2_rn(gg[0], gg[1]);
    __half2 bh = __floats2half2_rn(gg[2], gg[3]);
    *(uint2*)(&g_seq16[(size_t)(t * Bb + b) * Dd + n * HIDc]) =
        make_uint2(*reinterpret_cast<unsigned*>(&a), *reinterpret_cast<unsigned*>(&bh));
}

// ---------------- input GEMM on HMMA: Z^T[8192,1024] = w_ih @ seq^T + bias ----------------
#define BROW 40
__global__ void __launch_bounds__(512, 1)
k_zxt(const float* __restrict__ bih, const float* __restrict__ bhh) {
    __shared__ __align__(16) __half Bs[2][256 * BROW];
    int tid = threadIdx.x;
    int wi = tid >> 5;
    int lane = tid & 31;
    int wm = wi >> 2;
    int wn = wi & 3;
    int bm = blockIdx.y * 128;
    int bn = blockIdx.x * 256;

    int li0 = tid * 2;
    int row0 = li0 >> 2, c0 = li0 & 3;
    int li1 = li0 + 1;
    int row1 = li1 >> 2, c1 = li1 & 3;
    const __half* src0 = g_seq16 + (size_t)(bn + row0) * Dd + c0 * 8;
    const __half* src1 = g_seq16 + (size_t)(bn + row1) * Dd + c1 * 8;
    unsigned dst0 = smem_u32(&Bs[0][row0 * BROW + c0 * 8]);
    unsigned dst1 = smem_u32(&Bs[0][row1 * BROW + c1 * 8]);
    const unsigned bufB = 256 * BROW * 2;

    const uint4* Ap = ((const uint4*)g_wpk2) + ((size_t)(bm / 16 + wm * 2) * 128) * 32 + lane;
    int bfrag = (wn * 64 + (lane >> 2)) * BROW + (lane & 3) * 2;

    float acc[2][8][4];
#pragma unroll
    for (int a = 0; a < 2; a++)
#pragma unroll
        for (int b = 0; b < 8; b++)
#pragma unroll
            for (int c = 0; c < 4; c++) acc[a][b][c] = 0.f;

    asm volatile("cp.async.cg.shared.global [%0], [%1], 16;" :: "r"(dst0), "l"(src0));
    asm volatile("cp.async.cg.shared.global [%0], [%1], 16;" :: "r"(dst1), "l"(src1));
    asm volatile("cp.async.commit_group;");

    for (int kt = 0; kt < 64; kt++) {
        int buf = kt & 1;
        if (kt + 1 < 64) {
            unsigned off = ((kt + 1) & 1) * bufB;
            asm volatile("cp.async.cg.shared.global [%0], [%1], 16;"
                         :: "r"(dst0 + off), "l"(src0 + (kt + 1) * 32));
            asm volatile("cp.async.cg.shared.global [%0], [%1], 16;"
                         :: "r"(dst1 + off), "l"(src1 + (kt + 1) * 32));
            asm volatile("cp.async.commit_group;");
            asm volatile("cp.async.wait_group 1;");
        } else {
            asm volatile("cp.async.wait_group 0;");
        }
        __syncthreads();

        const __half* Bb_ = &Bs[buf][bfrag];
#pragma unroll
        for (int kk = 0; kk < 2; kk++) {
            int kc = kt * 2 + kk;
            uint4 a0 = Ap[(size_t)(0 * 128 + kc) * 32];
            uint4 a1 = Ap[(size_t)(1 * 128 + kc) * 32];
#pragma unroll
            for (int nt = 0; nt < 8; nt++) {
                unsigned b0 = *(const unsigned*)(Bb_ + nt * 8 * BROW + kk * 16);
                unsigned b1 = *(const unsigned*)(Bb_ + nt * 8 * BROW + kk * 16 + 8);
                asm volatile(
                    "mma.sync.aligned.m16n8k16.row.col.f32.f16.f16.f32 "
                    "{%0,%1,%2,%3}, {%4,%5,%6,%7}, {%8,%9}, {%0,%1,%2,%3};"
                    : "+f"(acc[0][nt][0]), "+f"(acc[0][nt][1]),
                      "+f"(acc[0][nt][2]), "+f"(acc[0][nt][3])
                    : "r"(a0.x), "r"(a0.y), "r"(a0.z), "r"(a0.w), "r"(b0), "r"(b1));
                asm volatile(
                    "mma.sync.aligned.m16n8k16.row.col.f32.f16.f16.f32 "
                    "{%0,%1,%2,%3}, {%4,%5,%6,%7}, {%8,%9}, {%0,%1,%2,%3};"
                    : "+f"(acc[1][nt][0]), "+f"(acc[1][nt][1]),
                      "+f"(acc[1][nt][2]), "+f"(acc[1][nt][3])
                    : "r"(a1.x), "r"(a1.y), "r"(a1.z), "r"(a1.w), "r"(b0), "r"(b1));
            }
        }
        __syncthreads();
    }

#pragma unroll
    for (int mtl = 0; mtl < 2; mtl++) {
        int m = bm + wm * 32 + mtl * 16 + (lane >> 2);
        float bA = bih[m] + bhh[m];
        float bB = bih[m + 8] + bhh[m + 8];
#pragma unroll
        for (int nt = 0; nt < 8; nt++) {
            int n = bn + wn * 64 + nt * 8 + (lane & 3) * 2;
            *(float2*)(&g_zxt[(size_t)m * 1024 + n]) =
                make_float2(acc[mtl][nt][0] + bA, acc[mtl][nt][1] + bA);
            *(float2*)(&g_zxt[(size_t)(m + 8) * 1024 + n]) =
                make_float2(acc[mtl][nt][2] + bB, acc[mtl][nt][3] + bB);
        }
    }
}

// ---------------- persistent LSTM: R10 structure + split accumulator chains ----------------
__global__ void __launch_bounds__(512, 1)
k_lstm(const float* __restrict__ wlin, const float* __restrict__ blin,
       float* __restrict__ out) {
    extern __shared__ __align__(16) char smem[];
    __half* h_h = (__half*)(smem + SM_HH);     // 8 x HROW fp16
    float*  fr  = (float*)(smem + SM_FR);      // 16 warps x 32 x 4
    float*  cs_ = (float*)(smem + SM_CS);      // c slice
    uint4*  ws  = (uint4*)(smem + SM_WS);      // weight cache: 16 warps x NCACHE x 32

    int tid = threadIdx.x;
    int wi = tid >> 5;
    int lane = tid & 31;
    int bid = blockIdx.x;
    int d0 = bid * 16;
    int ks = wi & 3;
    int mi = wi >> 2;
    const uint4* Abase = ((const uint4*)g_wpk) + ((size_t)(bid * 16 + mi * 4 + ks) * 32) * 32;
    int k0base = ks * 512;
    const __half* hb = &h_h[(lane >> 2) * HROW];
    uint4* wsw = ws + wi * (NCACHE * 32);

    int dd2 = tid >> 3;
    int bb = tid & 7;
    const float* zxb = g_zxt + (size_t)(d0 + dd2) * 1024 + bb;

    // preload weight cache, zero h, zero c
#pragma unroll
    for (int ch = 0; ch < NCACHE; ch++)
        wsw[ch * 32 + lane] = Abase[ch * 32 + lane];
    for (int u = tid; u < Bb * HROW / 8; u += 512)
        ((uint4*)h_h)[u] = make_uint4(0, 0, 0, 0);
    if (tid < 128) cs_[tid] = 0.f;
    __syncthreads();

    for (int t = 0; t < Tt; t++) {
        float zpre[4];
        if (tid < 128) {
            const float* zp = zxb + t * Bb;
#pragma unroll
            for (int g4 = 0; g4 < 4; g4++) zpre[g4] = zp[(size_t)g4 * 2097152];
        }

        if (t > 0) {
            const __half* hin = g_h16[t & 1];
#pragma unroll
            for (int u = 0; u < 4; u++) {
                int i = tid + u * 512;
                int b = i >> 8, k8 = i & 255;
                uint4 v = *(const uint4*)(hin + ((size_t)b << 11) + k8 * 8);
                *(uint4*)(&h_h[b * HROW + k8 * 8]) = v;
            }
            __syncthreads();
        }

        // 4 independent accumulator chains, static loops (global chunks then smem chunks)
        float a4[4][4];
#pragma unroll
        for (int cc = 0; cc < 4; cc++)
#pragma unroll
            for (int j = 0; j < 4; j++) a4[cc][j] = 0.f;

#pragma unroll
        for (int ci = 0; ci < NGLOB; ci++) {
            int ch = NCACHE + ci;
            uint4 a = Abase[ch * 32 + lane];
            int k = k0base + ch * 16 + (lane & 3) * 2;
            unsigned b0 = *(const unsigned*)(hb + k);
            unsigned b1 = *(const unsigned*)(hb + k + 8);
            float* c = a4[ci & 3];
            asm volatile(
                "mma.sync.aligned.m16n8k16.row.col.f32.f16.f16.f32 "
                "{%0,%1,%2,%3}, {%4,%5,%6,%7}, {%8,%9}, {%0,%1,%2,%3};"
                : "+f"(c[0]), "+f"(c[1]), "+f"(c[2]), "+f"(c[3])
                : "r"(a.x), "r"(a.y), "r"(a.z), "r"(a.w), "r"(b0), "r"(b1));
        }
#pragma unroll
        for (int ch = 0; ch < NCACHE; ch++) {
            uint4 a = wsw[ch * 32 + lane];
            int k = k0base + ch * 16 + (lane & 3) * 2;
            unsigned b0 = *(const unsigned*)(hb + k);
            unsigned b1 = *(const unsigned*)(hb + k + 8);
            float* c = a4[ch & 3];
            asm volatile(
                "mma.sync.aligned.m16n8k16.row.col.f32.f16.f16.f32 "
                "{%0,%1,%2,%3}, {%4,%5,%6,%7}, {%8,%9}, {%0,%1,%2,%3};"
                : "+f"(c[0]), "+f"(c[1]), "+f"(c[2]), "+f"(c[3])
                : "r"(a.x), "r"(a.y), "r"(a.z), "r"(a.w), "r"(b0), "r"(b1));
        }
        float c0 = (a4[0][0] + a4[1][0]) + (a4[2][0] + a4[3][0]);
        float c1 = (a4[0][1] + a4[1][1]) + (a4[2][1] + a4[3][1]);
        float c2 = (a4[0][2] + a4[1][2]) + (a4[2][2] + a4[3][2]);
        float c3 = (a4[0][3] + a4[1][3]) + (a4[2][3] + a4[3][3]);
        *(float4*)(&fr[((ks * 4 + mi) * 32 + lane) * 4]) = make_float4(c0, c1, c2, c3);
        __syncthreads();

        if (tid < 128) {
            int li = (dd2 & 7) * 4 + (bb >> 1);
            int ri = (bb & 1) + ((dd2 >> 3) << 1);
            float z[4];
#pragma unroll
            for (int g4 = 0; g4 < 4; g4++) {
                float s = zpre[g4];
#pragma unroll
                for (int kss = 0; kss < 4; kss++)
                    s += fr[((kss * 4 + g4) * 32 + li) * 4 + ri];
                z[g4] = s;
            }
            float ig = 1.f / (1.f + expf(-z[0]));
            float fg = 1.f / (1.f + expf(-z[1]));
            float gg = tanhf(z[2]);
            float og = 1.f / (1.f + expf(-z[3]));
            float cn = fg * cs_[bb * 16 + dd2] + ig * gg;
            cs_[bb * 16 + dd2] = cn;
            float hn = og * tanhf(cn);
            int par = (t + 1) & 1;
            g_h16[par][bb * Dd + d0 + dd2] = __float2half(hn);
            g_h[par][bb * Dd + d0 + dd2] = hn;
        }
        __syncthreads();

        // grid barrier: single counter, release-arrive + acquire-poll (proven best)
        if (tid == 0) {
            int* bar = &g_bar[t];
            asm volatile("red.release.gpu.add.u32 [%0], 1;" :: "l"(bar) : "memory");
            unsigned v;
            do {
                asm volatile("ld.acquire.gpu.u32 %0, [%1];" : "=r"(v) : "l"(bar) : "memory");
            } while (v < 128);
        }
        __syncthreads();
    }

    // final linear: h_T in g_h[0]
    {
        int col = bid * 4 + (wi & 3);
        int p = wi >> 2;
        const float* wl = wlin + (size_t)col * Dd + lane * 4;
        const float* h0 = g_h[0] + (size_t)(2 * p) * Dd + lane * 4;
        const float* h1 = g_h[0] + (size_t)(2 * p + 1) * Dd + lane * 4;
        ull s0 = 0ull, s1 = 0ull;
#pragma unroll 4
        for (int it = 0; it < 16; it++) {
            int ko = it * 128;
            ulonglong2 wv = *(const ulonglong2*)(wl + ko);
            ulonglong2 hv0 = *(const ulonglong2*)(h0 + ko);
            ulonglong2 hv1 = *(const ulonglong2*)(h1 + ko);
            ffma2(s0, wv.x, hv0.x);
            ffma2(s0, wv.y, hv0.y);
            ffma2(s1, wv.x, hv1.x);
            ffma2(s1, wv.y, hv1.y);
        }
        float f0 = fsum2(s0), f1 = fsum2(s1);
#pragma unroll
        for (int d = 16; d; d >>= 1) {
            f0 += __shfl_xor_sync(0xffffffffu, f0, d);
            f1 += __shfl_xor_sync(0xffffffffu, f1, d);
        }
        if (lane == 0) {
            float bl = blin[col];
            out[(2 * p) * Nn + col]     = f0 + bl;
            out[(2 * p + 1) * Nn + col] = f1 + bl;
        }
    }
}

// ---------------- launch ----------------
extern "C" void kernel_launch(void* const* d_in, const int* in_sizes, int n_in,
                              void* d_out, int out_size) {
    const float* x    = (const float*)d_in[0];
    const float* gw   = (const float*)d_in[1];
    const float* as_  = (const float*)d_in[2];
    const float* ad_  = (const float*)d_in[3];
    const float* gb   = (const float*)d_in[4];
    const float* wih  = (const float*)d_in[5];
    const float* whh  = (const float*)d_in[6];
    const float* bih  = (const float*)d_in[7];
    const float* bhh  = (const float*)d_in[8];
    const float* wlin = (const float*)d_in[9];
    const float* blin = (const float*)d_in[10];
    const int*   ei   = (const int*)d_in[11];
    (void)in_sizes; (void)n_in; (void)out_size;

    static int smem_set = 0;
    if (!smem_set) {
        cudaFuncSetAttribute(k_lstm, cudaFuncAttributeMaxDynamicSharedMemorySize, SM_TOTAL);
        smem_set = 1;
    }

    // pack both weight matrices (one launch)
    k_wcvt_all<<<8192, 512>>>(whh, wih);

    // fused CSR build + consts + barrier clear (one block)
    k_graph<<<1, 512>>>(ei, gw, as_, ad_);

    // GAT -> g_seq16 [1024, 2048] fp16
    k_gat_b0<<<Tt, Nn>>>(x, gw, gb);
    k_gat_rest<<<1792, 256>>>(x, gw, gb);

    // Input projection (HMMA): Z^T = w_ih @ seq^T + bias
    {
        dim3 grid(4, 64);
        k_zxt<<<grid, 512>>>(bih, bhh);
    }

    // Persistent LSTM + final linear
    k_lstm<<<128, 512, SM_TOTAL>>>(wlin, blin, (float*)d_out);
}

// round 15
// speedup vs baseline: 2.1271x; 1.0029x over previous
#include <cuda_runtime.h>
#include <cuda_fp16.h>
#include <math.h>

// Problem constants
#define Bb   8
#define Tt   128
#define Nn   512
#define HIDc 4
#define Dd   2048
#define Ee   16384
#define FD   8192
#define NEG  0.2f

// k_lstm smem layout (dynamic, opt-in)
#define HROW   2056
#define NCACHE 22                     // k-chunks cached in smem (of 32)
#define NGLOB  (32 - NCACHE)
#define SM_HH    0
#define SM_FR    32896                // 8*2056*2
#define SM_CS    (SM_FR + 8192)
#define SM_WS    (SM_CS + 512)        // 41600, 16B aligned
#define SM_TOTAL (SM_WS + 16 * NCACHE * 32 * 16)   // + 176 KB = 221824

// ---------------- device scratch (no allocations allowed) ----------------
__device__ __align__(256) __half g_seq16[1024 * 2048];  // [T*B, D] GAT out fp16, 4 MB
__device__ __align__(256) float g_zxt[8192u * 1024u];   // Z^T [4D, T*B], 32 MB
__device__ __align__(256) unsigned g_wpk[8388608];      // w_hh packed A-frags, 32 MB
__device__ __align__(256) unsigned g_wpk2[8388608];     // w_ih packed A-frags, 32 MB
__device__ __align__(256) float  g_h[2][Bb * Dd];       // fp32 hidden (final linear)
__device__ __align__(256) __half g_h16[2][Bb * Dd];     // fp16 hidden (mma B operand)
__device__ int   g_bar[Tt];
__device__ int   g_deg[Nn];
__device__ int   g_off[Nn];
__device__ int   g_csr[Ee];
__device__ float g_cs, g_cd;

// ---------------- helpers ----------------
typedef unsigned long long ull;

__device__ __forceinline__ ull pk2(float x, float y) {
    ull r;
    asm("mov.b64 %0, {%1, %2};" : "=l"(r) : "f"(x), "f"(y));
    return r;
}
__device__ __forceinline__ void ffma2(ull &d, ull a, ull b) {
    asm("fma.rn.f32x2 %0, %1, %2, %0;" : "+l"(d) : "l"(a), "l"(b));
}
__device__ __forceinline__ float fsum2(ull v) {
    float x, y;
    asm("mov.b64 {%0, %1}, %2;" : "=f"(x), "=f"(y) : "l"(v));
    return x + y;
}
__device__ __forceinline__ unsigned smem_u32(const void* p) {
    unsigned a;
    asm("{ .reg .u64 t; cvta.to.shared.u64 t, %1; cvt.u32.u64 %0, t; }"
        : "=r"(a) : "l"(p));
    return a;
}

// ---------------- w_hh fp32 -> fp16 packed m16n8k16 A-frag order ----------------
__global__ void k_wcvt_hh(const float* __restrict__ whh) {
    unsigned idx = blockIdx.x * 512 + threadIdx.x;
    if (idx >= 2097152u) return;
    unsigned lane  = idx & 31;
    unsigned ch    = (idx >> 5) & 31;
    unsigned outer = idx >> 10;
    unsigned ks  = outer & 3;
    unsigned mi  = (outer >> 2) & 3;
    unsigned bid = outer >> 4;
    unsigned rbase = mi * Dd + bid * 16 + (lane >> 2);
    unsigned kbase = ks * 512 + ch * 16 + (lane & 3) * 2;
    unsigned r[4];
#pragma unroll
    for (int rr = 0; rr < 4; rr++) {
        unsigned row = rbase + (rr & 1) * 8;
        unsigned k   = kbase + ((rr >> 1) & 1) * 8;
        float2 v = *(const float2*)(whh + (size_t)row * Dd + k);
        __half2 h = __floats2half2_rn(v.x, v.y);
        r[rr] = *reinterpret_cast<unsigned*>(&h);
    }
    ((uint4*)g_wpk)[idx] = make_uint4(r[0], r[1], r[2], r[3]);
}

// ---------------- w_ih fp32 -> fp16 packed A-frag order ----------------
__global__ void k_wcvt_ih(const float* __restrict__ wih) {
    unsigned idx = blockIdx.x * 512 + threadIdx.x;
    if (idx >= 2097152u) return;
    unsigned lane = idx & 31;
    unsigned kc   = (idx >> 5) & 127;
    unsigned mt   = idx >> 12;
    unsigned rbase = mt * 16 + (lane >> 2);
    unsigned kbase = kc * 16 + (lane & 3) * 2;
    unsigned r[4];
#pragma unroll
    for (int rr = 0; rr < 4; rr++) {
        unsigned row = rbase + (rr & 1) * 8;
        unsigned k   = kbase + ((rr >> 1) & 1) * 8;
        float2 v = *(const float2*)(wih + (size_t)row * Dd + k);
        __half2 h = __floats2half2_rn(v.x, v.y);
        r[rr] = *reinterpret_cast<unsigned*>(&h);
    }
    ((uint4*)g_wpk2)[idx] = make_uint4(r[0], r[1], r[2], r[3]);
}

// ---------------- fused CSR build: consts + degree + scan + fill (1 block) ----------------
__global__ void __launch_bounds__(512)
k_graph(const int* __restrict__ ei, const float* __restrict__ W,
        const float* __restrict__ as_, const float* __restrict__ ad_) {
    __shared__ int sdeg[Nn];
    __shared__ int s[Nn];
    __shared__ int scur[Nn];
    int tid = threadIdx.x;
    if (tid == 0) {
        float cs = 0.f, cd = 0.f;
        for (int k = 0; k < HIDc; k++) { cs += W[k] * as_[k]; cd += W[k] * ad_[k]; }
        g_cs = cs; g_cd = cd;
    }
    sdeg[tid] = 0;
    if (tid < Tt) g_bar[tid] = 0;
    __syncthreads();
    for (int e = tid; e < Ee; e += 512) atomicAdd(&sdeg[ei[Ee + e]], 1);
    __syncthreads();
    int d = sdeg[tid];
    s[tid] = d;
    __syncthreads();
    for (int off = 1; off < Nn; off <<= 1) {
        int t = 0;
        if (tid >= off) t = s[tid - off];
        __syncthreads();
        s[tid] += t;
        __syncthreads();
    }
    g_deg[tid] = d;
    g_off[tid] = s[tid] - d;
    scur[tid] = s[tid] - d;
    __syncthreads();
    for (int e = tid; e < Ee; e += 512) {
        int src = ei[e];
        int dst = ei[Ee + e];
        int pos = atomicAdd(&scur[dst], 1);
        g_csr[pos] = src;
    }
}

// GAT for batch-0 nodes. One block per t. Writes fp16.
__global__ void k_gat_b0(const float* __restrict__ x, const float* __restrict__ W,
                         const float* __restrict__ bias) {
    __shared__ float xs[Nn];
    int t = blockIdx.x;
    int i = threadIdx.x;
    xs[i] = x[t * Nn + i];
    __syncthreads();
    float cs = g_cs, cd = g_cd;
    float xi = xs[i];
    float es = xi * (cs + cd);
    es = es > 0.f ? es : NEG * es;
    int beg = g_off[i], end = beg + g_deg[i];
    float m = es;
    for (int e = beg; e < end; e++) {
        float v = cs * xs[g_csr[e]] + cd * xi;
        v = v > 0.f ? v : NEG * v;
        m = fmaxf(m, v);
    }
    float den = expf(es - m);
    float ssum = den * xi;
    for (int e = beg; e < end; e++) {
        float xsrc = xs[g_csr[e]];
        float v = cs * xsrc + cd * xi;
        v = v > 0.f ? v : NEG * v;
        float w = expf(v - m);
        den += w;
        ssum += w * xsrc;
    }
    float sA = ssum / den;
    float gg[4];
#pragma unroll
    for (int k = 0; k < HIDc; k++) {
        float g = fmaf(sA, W[k], bias[k]);
        gg[k] = g > 0.f ? g : 0.f;
    }
    __half2 a = __floats2half2_rn(gg[0], gg[1]);
    __half2 b = __floats2half2_rn(gg[2], gg[3]);
    *(uint2*)(&g_seq16[(size_t)(t * Bb) * Dd + i * HIDc]) =
        make_uint2(*reinterpret_cast<unsigned*>(&a), *reinterpret_cast<unsigned*>(&b));
}

// GAT for batches 1..7: self-loop only => s = x. Writes fp16.
__global__ void k_gat_rest(const float* __restrict__ x, const float* __restrict__ W,
                           const float* __restrict__ bias) {
    int idx = blockIdx.x * 256 + threadIdx.x;
    if (idx >= Tt * (Bb - 1) * Nn) return;
    int t = idx / ((Bb - 1) * Nn);
    int r = idx - t * (Bb - 1) * Nn;
    int b = 1 + (r >> 9);
    int n = r & (Nn - 1);
    float xi = x[((size_t)b * Tt + t) * Nn + n];
    float gg[4];
#pragma unroll
    for (int k = 0; k < HIDc; k++) {
        float g = fmaf(xi, W[k], bias[k]);
        gg[k] = g > 0.f ? g : 0.f;
    }
    __half2 a = __floats2half2_rn(gg[0], gg[1]);
    __half2 bh = __floats2half2_rn(gg[2], gg[3]);
    *(uint2*)(&g_seq16[(size_t)(t * Bb + b) * Dd + n * HIDc]) =
        make_uint2(*reinterpret_cast<unsigned*>(&a), *reinterpret_cast<unsigned*>(&bh));
}

// ---------------- input GEMM on HMMA: Z^T[8192,1024] = w_ih @ seq^T + bias ----------------
#define BROW 40
__global__ void __launch_bounds__(512, 1)
k_zxt(const float* __restrict__ bih, const float* __restrict__ bhh) {
    __shared__ __align__(16) __half Bs[2][256 * BROW];
    int tid = threadIdx.x;
    int wi = tid >> 5;
    int lane = tid & 31;
    int wm = wi >> 2;
    int wn = wi & 3;
    int bm = blockIdx.y * 128;
    int bn = blockIdx.x * 256;

    int li0 = tid * 2;
    int row0 = li0 >> 2, c0 = li0 & 3;
    int li1 = li0 + 1;
    int row1 = li1 >> 2, c1 = li1 & 3;
    const __half* src0 = g_seq16 + (size_t)(bn + row0) * Dd + c0 * 8;
    const __half* src1 = g_seq16 + (size_t)(bn + row1) * Dd + c1 * 8;
    unsigned dst0 = smem_u32(&Bs[0][row0 * BROW + c0 * 8]);
    unsigned dst1 = smem_u32(&Bs[0][row1 * BROW + c1 * 8]);
    const unsigned bufB = 256 * BROW * 2;

    const uint4* Ap = ((const uint4*)g_wpk2) + ((size_t)(bm / 16 + wm * 2) * 128) * 32 + lane;
    int bfrag = (wn * 64 + (lane >> 2)) * BROW + (lane & 3) * 2;

    float acc[2][8][4];
#pragma unroll
    for (int a = 0; a < 2; a++)
#pragma unroll
        for (int b = 0; b < 8; b++)
#pragma unroll
            for (int c = 0; c < 4; c++) acc[a][b][c] = 0.f;

    asm volatile("cp.async.cg.shared.global [%0], [%1], 16;" :: "r"(dst0), "l"(src0));
    asm volatile("cp.async.cg.shared.global [%0], [%1], 16;" :: "r"(dst1), "l"(src1));
    asm volatile("cp.async.commit_group;");

    for (int kt = 0; kt < 64; kt++) {
        int buf = kt & 1;
        if (kt + 1 < 64) {
            unsigned off = ((kt + 1) & 1) * bufB;
            asm volatile("cp.async.cg.shared.global [%0], [%1], 16;"
                         :: "r"(dst0 + off), "l"(src0 + (kt + 1) * 32));
            asm volatile("cp.async.cg.shared.global [%0], [%1], 16;"
                         :: "r"(dst1 + off), "l"(src1 + (kt + 1) * 32));
            asm volatile("cp.async.commit_group;");
            asm volatile("cp.async.wait_group 1;");
        } else {
            asm volatile("cp.async.wait_group 0;");
        }
        __syncthreads();

        const __half* Bb_ = &Bs[buf][bfrag];
#pragma unroll
        for (int kk = 0; kk < 2; kk++) {
            int kc = kt * 2 + kk;
            uint4 a0 = Ap[(size_t)(0 * 128 + kc) * 32];
            uint4 a1 = Ap[(size_t)(1 * 128 + kc) * 32];
#pragma unroll
            for (int nt = 0; nt < 8; nt++) {
                unsigned b0 = *(const unsigned*)(Bb_ + nt * 8 * BROW + kk * 16);
                unsigned b1 = *(const unsigned*)(Bb_ + nt * 8 * BROW + kk * 16 + 8);
                asm volatile(
                    "mma.sync.aligned.m16n8k16.row.col.f32.f16.f16.f32 "
                    "{%0,%1,%2,%3}, {%4,%5,%6,%7}, {%8,%9}, {%0,%1,%2,%3};"
                    : "+f"(acc[0][nt][0]), "+f"(acc[0][nt][1]),
                      "+f"(acc[0][nt][2]), "+f"(acc[0][nt][3])
                    : "r"(a0.x), "r"(a0.y), "r"(a0.z), "r"(a0.w), "r"(b0), "r"(b1));
                asm volatile(
                    "mma.sync.aligned.m16n8k16.row.col.f32.f16.f16.f32 "
                    "{%0,%1,%2,%3}, {%4,%5,%6,%7}, {%8,%9}, {%0,%1,%2,%3};"
                    : "+f"(acc[1][nt][0]), "+f"(acc[1][nt][1]),
                      "+f"(acc[1][nt][2]), "+f"(acc[1][nt][3])
                    : "r"(a1.x), "r"(a1.y), "r"(a1.z), "r"(a1.w), "r"(b0), "r"(b1));
            }
        }
        __syncthreads();
    }

#pragma unroll
    for (int mtl = 0; mtl < 2; mtl++) {
        int m = bm + wm * 32 + mtl * 16 + (lane >> 2);
        float bA = bih[m] + bhh[m];
        float bB = bih[m + 8] + bhh[m + 8];
#pragma unroll
        for (int nt = 0; nt < 8; nt++) {
            int n = bn + wn * 64 + nt * 8 + (lane & 3) * 2;
            *(float2*)(&g_zxt[(size_t)m * 1024 + n]) =
                make_float2(acc[mtl][nt][0] + bA, acc[mtl][nt][1] + bA);
            *(float2*)(&g_zxt[(size_t)(m + 8) * 1024 + n]) =
                make_float2(acc[mtl][nt][2] + bB, acc[mtl][nt][3] + bB);
        }
    }
}

// ---------------- persistent LSTM: exact R10 mainloop (best known) ----------------
__global__ void __launch_bounds__(512, 1)
k_lstm(const float* __restrict__ wlin, const float* __restrict__ blin,
       float* __restrict__ out) {
    extern __shared__ __align__(16) char smem[];
    __half* h_h = (__half*)(smem + SM_HH);
    float*  fr  = (float*)(smem + SM_FR);
    float*  cs_ = (float*)(smem + SM_CS);
    uint4*  ws  = (uint4*)(smem + SM_WS);

    int tid = threadIdx.x;
    int wi = tid >> 5;
    int lane = tid & 31;
    int bid = blockIdx.x;
    int d0 = bid * 16;
    int ks = wi & 3;
    int mi = wi >> 2;
    const uint4* Abase = ((const uint4*)g_wpk) + ((size_t)(bid * 16 + mi * 4 + ks) * 32) * 32;
    int k0base = ks * 512;
    const __half* hb = &h_h[(lane >> 2) * HROW];
    uint4* wsw = ws + wi * (NCACHE * 32);

    int dd2 = tid >> 3;
    int bb = tid & 7;
    const float* zxb = g_zxt + (size_t)(d0 + dd2) * 1024 + bb;

#pragma unroll
    for (int ch = 0; ch < NCACHE; ch++)
        wsw[ch * 32 + lane] = Abase[ch * 32 + lane];
    for (int u = tid; u < Bb * HROW / 8; u += 512)
        ((uint4*)h_h)[u] = make_uint4(0, 0, 0, 0);
    if (tid < 128) cs_[tid] = 0.f;
    __syncthreads();

    for (int t = 0; t < Tt; t++) {
        float zpre[4];
        if (tid < 128) {
            const float* zp = zxb + t * Bb;
#pragma unroll
            for (int g4 = 0; g4 < 4; g4++) zpre[g4] = zp[(size_t)g4 * 2097152];
        }

        if (t > 0) {
            const __half* hin = g_h16[t & 1];
#pragma unroll
            for (int u = 0; u < 4; u++) {
                int i = tid + u * 512;
                int b = i >> 8, k8 = i & 255;
                uint4 v = *(const uint4*)(hin + ((size_t)b << 11) + k8 * 8);
                *(uint4*)(&h_h[b * HROW + k8 * 8]) = v;
            }
            __syncthreads();
        }

        float c0 = 0.f, c1 = 0.f, c2 = 0.f, c3 = 0.f;
#pragma unroll
        for (int ci = 0; ci < NGLOB; ci++) {
            int ch = NCACHE + ci;
            uint4 a = Abase[ch * 32 + lane];
            int k = k0base + ch * 16 + (lane & 3) * 2;
            unsigned b0 = *(const unsigned*)(hb + k);
            unsigned b1 = *(const unsigned*)(hb + k + 8);
            asm volatile(
                "mma.sync.aligned.m16n8k16.row.col.f32.f16.f16.f32 "
                "{%0,%1,%2,%3}, {%4,%5,%6,%7}, {%8,%9}, {%0,%1,%2,%3};"
                : "+f"(c0), "+f"(c1), "+f"(c2), "+f"(c3)
                : "r"(a.x), "r"(a.y), "r"(a.z), "r"(a.w), "r"(b0), "r"(b1));
        }
#pragma unroll
        for (int ch = 0; ch < NCACHE; ch++) {
            uint4 a = wsw[ch * 32 + lane];
            int k = k0base + ch * 16 + (lane & 3) * 2;
            unsigned b0 = *(const unsigned*)(hb + k);
            unsigned b1 = *(const unsigned*)(hb + k + 8);
            asm volatile(
                "mma.sync.aligned.m16n8k16.row.col.f32.f16.f16.f32 "
                "{%0,%1,%2,%3}, {%4,%5,%6,%7}, {%8,%9}, {%0,%1,%2,%3};"
                : "+f"(c0), "+f"(c1), "+f"(c2), "+f"(c3)
                : "r"(a.x), "r"(a.y), "r"(a.z), "r"(a.w), "r"(b0), "r"(b1));
        }
        *(float4*)(&fr[((ks * 4 + mi) * 32 + lane) * 4]) = make_float4(c0, c1, c2, c3);
        __syncthreads();

        if (tid < 128) {
            int li = (dd2 & 7) * 4 + (bb >> 1);
            int ri = (bb & 1) + ((dd2 >> 3) << 1);
            float z[4];
#pragma unroll
            for (int g4 = 0; g4 < 4; g4++) {
                float s = zpre[g4];
#pragma unroll
                for (int kss = 0; kss < 4; kss++)
                    s += fr[((kss * 4 + g4) * 32 + li) * 4 + ri];
                z[g4] = s;
            }
            float ig = 1.f / (1.f + expf(-z[0]));
            float fg = 1.f / (1.f + expf(-z[1]));
            float gg = tanhf(z[2]);
            float og = 1.f / (1.f + expf(-z[3]));
            float cn = fg * cs_[bb * 16 + dd2] + ig * gg;
            cs_[bb * 16 + dd2] = cn;
            float hn = og * tanhf(cn);
            int par = (t + 1) & 1;
            g_h16[par][bb * Dd + d0 + dd2] = __float2half(hn);
            g_h[par][bb * Dd + d0 + dd2] = hn;
        }
        __syncthreads();

        // grid barrier: single counter, release-arrive + acquire-poll (proven best)
        if (tid == 0) {
            int* bar = &g_bar[t];
            asm volatile("red.release.gpu.add.u32 [%0], 1;" :: "l"(bar) : "memory");
            unsigned v;
            do {
                asm volatile("ld.acquire.gpu.u32 %0, [%1];" : "=r"(v) : "l"(bar) : "memory");
            } while (v < 128);
        }
        __syncthreads();
    }

    // final linear: h_T in g_h[0]
    {
        int col = bid * 4 + (wi & 3);
        int p = wi >> 2;
        const float* wl = wlin + (size_t)col * Dd + lane * 4;
        const float* h0 = g_h[0] + (size_t)(2 * p) * Dd + lane * 4;
        const float* h1 = g_h[0] + (size_t)(2 * p + 1) * Dd + lane * 4;
        ull s0 = 0ull, s1 = 0ull;
#pragma unroll 4
        for (int it = 0; it < 16; it++) {
            int ko = it * 128;
            ulonglong2 wv = *(const ulonglong2*)(wl + ko);
            ulonglong2 hv0 = *(const ulonglong2*)(h0 + ko);
            ulonglong2 hv1 = *(const ulonglong2*)(h1 + ko);
            ffma2(s0, wv.x, hv0.x);
            ffma2(s0, wv.y, hv0.y);
            ffma2(s1, wv.x, hv1.x);
            ffma2(s1, wv.y, hv1.y);
        }
        float f0 = fsum2(s0), f1 = fsum2(s1);
#pragma unroll
        for (int d = 16; d; d >>= 1) {
            f0 += __shfl_xor_sync(0xffffffffu, f0, d);
            f1 += __shfl_xor_sync(0xffffffffu, f1, d);
        }
        if (lane == 0) {
            float bl = blin[col];
            out[(2 * p) * Nn + col]     = f0 + bl;
            out[(2 * p + 1) * Nn + col] = f1 + bl;
        }
    }
}

// ---------------- launch: fork-join so weight packing overlaps GAT/zxt ----------------
extern "C" void kernel_launch(void* const* d_in, const int* in_sizes, int n_in,
                              void* d_out, int out_size) {
    const float* x    = (const float*)d_in[0];
    const float* gw   = (const float*)d_in[1];
    const float* as_  = (const float*)d_in[2];
    const float* ad_  = (const float*)d_in[3];
    const float* gb   = (const float*)d_in[4];
    const float* wih  = (const float*)d_in[5];
    const float* whh  = (const float*)d_in[6];
    const float* bih  = (const float*)d_in[7];
    const float* bhh  = (const float*)d_in[8];
    const float* wlin = (const float*)d_in[9];
    const float* blin = (const float*)d_in[10];
    const int*   ei   = (const int*)d_in[11];
    (void)in_sizes; (void)n_in; (void)out_size;

    static int inited = 0;
    static cudaStream_t s2;
    static cudaEvent_t ev_fork, ev_wih, ev_whh;
    if (!inited) {
        cudaFuncSetAttribute(k_lstm, cudaFuncAttributeMaxDynamicSharedMemorySize, SM_TOTAL);
        cudaStreamCreateWithFlags(&s2, cudaStreamNonBlocking);
        cudaEventCreateWithFlags(&ev_fork, cudaEventDisableTiming);
        cudaEventCreateWithFlags(&ev_wih, cudaEventDisableTiming);
        cudaEventCreateWithFlags(&ev_whh, cudaEventDisableTiming);
        inited = 1;
    }

    // fork: side stream packs weights while main stream does graph + GAT
    cudaEventRecord(ev_fork, 0);
    cudaStreamWaitEvent(s2, ev_fork, 0);
    k_wcvt_ih<<<4096, 512, 0, s2>>>(wih);
    cudaEventRecord(ev_wih, s2);
    k_wcvt_hh<<<4096, 512, 0, s2>>>(whh);
    cudaEventRecord(ev_whh, s2);

    // main stream: CSR build + GAT (independent of weight packing)
    k_graph<<<1, 512>>>(ei, gw, as_, ad_);
    k_gat_b0<<<Tt, Nn>>>(x, gw, gb);
    k_gat_rest<<<1792, 256>>>(x, gw, gb);

    // zxt needs packed w_ih
    cudaStreamWaitEvent(0, ev_wih, 0);
    {
        dim3 grid(4, 64);
        k_zxt<<<grid, 512>>>(bih, bhh);
    }

    // lstm needs packed w_hh
    cudaStreamWaitEvent(0, ev_whh, 0);
    k_lstm<<<128, 512, SM_TOTAL>>>(wlin, blin, (float*)d_out);
}

// round 16
// speedup vs baseline: 2.3595x; 1.1092x over previous
#include <cuda_runtime.h>
#include <cuda_fp16.h>
#include <math.h>

// Problem constants
#define Bb   8
#define Tt   128
#define Nn   512
#define HIDc 4
#define Dd   2048
#define Ee   16384
#define FD   8192
#define NEG  0.2f

// k_lstm smem layout (dynamic, opt-in)
#define HROW   2056
#define NCACHE 22                     // k-chunks cached in smem (of 32)
#define NGLOB  (32 - NCACHE)          // k-chunks pinned in REGISTERS
#define SM_HH    0
#define SM_FR    32896                // 8*2056*2
#define SM_CS    (SM_FR + 8192)
#define SM_WS    (SM_CS + 512)        // 41600, 16B aligned
#define SM_TOTAL (SM_WS + 16 * NCACHE * 32 * 16)   // + 176 KB = 221824

// ---------------- device scratch (no allocations allowed) ----------------
__device__ __align__(256) __half g_seq16[1024 * 2048];  // [T*B, D] GAT out fp16, 4 MB
__device__ __align__(256) float g_zxt[8192u * 1024u];   // Z^T [4D, T*B], 32 MB
__device__ __align__(256) unsigned g_wpk[8388608];      // w_hh packed A-frags, 32 MB
__device__ __align__(256) unsigned g_wpk2[8388608];     // w_ih packed A-frags, 32 MB
__device__ __align__(256) float  g_h[2][Bb * Dd];       // fp32 hidden (final linear)
__device__ __align__(256) __half g_h16[2][Bb * Dd];     // fp16 hidden (mma B operand)
__device__ int   g_bar[Tt];
__device__ int   g_deg[Nn];
__device__ int   g_off[Nn];
__device__ int   g_csr[Ee];
__device__ float g_cs, g_cd;

// ---------------- helpers ----------------
typedef unsigned long long ull;

__device__ __forceinline__ ull pk2(float x, float y) {
    ull r;
    asm("mov.b64 %0, {%1, %2};" : "=l"(r) : "f"(x), "f"(y));
    return r;
}
__device__ __forceinline__ void ffma2(ull &d, ull a, ull b) {
    asm("fma.rn.f32x2 %0, %1, %2, %0;" : "+l"(d) : "l"(a), "l"(b));
}
__device__ __forceinline__ float fsum2(ull v) {
    float x, y;
    asm("mov.b64 {%0, %1}, %2;" : "=f"(x), "=f"(y) : "l"(v));
    return x + y;
}
__device__ __forceinline__ unsigned smem_u32(const void* p) {
    unsigned a;
    asm("{ .reg .u64 t; cvta.to.shared.u64 t, %1; cvt.u32.u64 %0, t; }"
        : "=r"(a) : "l"(p));
    return a;
}

// ---------------- w_hh fp32 -> fp16 packed m16n8k16 A-frag order ----------------
__global__ void k_wcvt_hh(const float* __restrict__ whh) {
    unsigned idx = blockIdx.x * 512 + threadIdx.x;
    if (idx >= 2097152u) return;
    unsigned lane  = idx & 31;
    unsigned ch    = (idx >> 5) & 31;
    unsigned outer = idx >> 10;
    unsigned ks  = outer & 3;
    unsigned mi  = (outer >> 2) & 3;
    unsigned bid = outer >> 4;
    unsigned rbase = mi * Dd + bid * 16 + (lane >> 2);
    unsigned kbase = ks * 512 + ch * 16 + (lane & 3) * 2;
    unsigned r[4];
#pragma unroll
    for (int rr = 0; rr < 4; rr++) {
        unsigned row = rbase + (rr & 1) * 8;
        unsigned k   = kbase + ((rr >> 1) & 1) * 8;
        float2 v = *(const float2*)(whh + (size_t)row * Dd + k);
        __half2 h = __floats2half2_rn(v.x, v.y);
        r[rr] = *reinterpret_cast<unsigned*>(&h);
    }
    ((uint4*)g_wpk)[idx] = make_uint4(r[0], r[1], r[2], r[3]);
}

// ---------------- w_ih fp32 -> fp16 packed A-frag order ----------------
__global__ void k_wcvt_ih(const float* __restrict__ wih) {
    unsigned idx = blockIdx.x * 512 + threadIdx.x;
    if (idx >= 2097152u) return;
    unsigned lane = idx & 31;
    unsigned kc   = (idx >> 5) & 127;
    unsigned mt   = idx >> 12;
    unsigned rbase = mt * 16 + (lane >> 2);
    unsigned kbase = kc * 16 + (lane & 3) * 2;
    unsigned r[4];
#pragma unroll
    for (int rr = 0; rr < 4; rr++) {
        unsigned row = rbase + (rr & 1) * 8;
        unsigned k   = kbase + ((rr >> 1) & 1) * 8;
        float2 v = *(const float2*)(wih + (size_t)row * Dd + k);
        __half2 h = __floats2half2_rn(v.x, v.y);
        r[rr] = *reinterpret_cast<unsigned*>(&h);
    }
    ((uint4*)g_wpk2)[idx] = make_uint4(r[0], r[1], r[2], r[3]);
}

// ---------------- fused CSR build: consts + degree + scan + fill (1 block) ----------------
__global__ void __launch_bounds__(512)
k_graph(const int* __restrict__ ei, const float* __restrict__ W,
        const float* __restrict__ as_, const float* __restrict__ ad_) {
    __shared__ int sdeg[Nn];
    __shared__ int s[Nn];
    __shared__ int scur[Nn];
    int tid = threadIdx.x;
    if (tid == 0) {
        float cs = 0.f, cd = 0.f;
        for (int k = 0; k < HIDc; k++) { cs += W[k] * as_[k]; cd += W[k] * ad_[k]; }
        g_cs = cs; g_cd = cd;
    }
    sdeg[tid] = 0;
    if (tid < Tt) g_bar[tid] = 0;
    __syncthreads();
    for (int e = tid; e < Ee; e += 512) atomicAdd(&sdeg[ei[Ee + e]], 1);
    __syncthreads();
    int d = sdeg[tid];
    s[tid] = d;
    __syncthreads();
    for (int off = 1; off < Nn; off <<= 1) {
        int t = 0;
        if (tid >= off) t = s[tid - off];
        __syncthreads();
        s[tid] += t;
        __syncthreads();
    }
    g_deg[tid] = d;
    g_off[tid] = s[tid] - d;
    scur[tid] = s[tid] - d;
    __syncthreads();
    for (int e = tid; e < Ee; e += 512) {
        int src = ei[e];
        int dst = ei[Ee + e];
        int pos = atomicAdd(&scur[dst], 1);
        g_csr[pos] = src;
    }
}

// GAT for batch-0 nodes. One block per t. Writes fp16.
__global__ void k_gat_b0(const float* __restrict__ x, const float* __restrict__ W,
                         const float* __restrict__ bias) {
    __shared__ float xs[Nn];
    int t = blockIdx.x;
    int i = threadIdx.x;
    xs[i] = x[t * Nn + i];
    __syncthreads();
    float cs = g_cs, cd = g_cd;
    float xi = xs[i];
    float es = xi * (cs + cd);
    es = es > 0.f ? es : NEG * es;
    int beg = g_off[i], end = beg + g_deg[i];
    float m = es;
    for (int e = beg; e < end; e++) {
        float v = cs * xs[g_csr[e]] + cd * xi;
        v = v > 0.f ? v : NEG * v;
        m = fmaxf(m, v);
    }
    float den = expf(es - m);
    float ssum = den * xi;
    for (int e = beg; e < end; e++) {
        float xsrc = xs[g_csr[e]];
        float v = cs * xsrc + cd * xi;
        v = v > 0.f ? v : NEG * v;
        float w = expf(v - m);
        den += w;
        ssum += w * xsrc;
    }
    float sA = ssum / den;
    float gg[4];
#pragma unroll
    for (int k = 0; k < HIDc; k++) {
        float g = fmaf(sA, W[k], bias[k]);
        gg[k] = g > 0.f ? g : 0.f;
    }
    __half2 a = __floats2half2_rn(gg[0], gg[1]);
    __half2 b = __floats2half2_rn(gg[2], gg[3]);
    *(uint2*)(&g_seq16[(size_t)(t * Bb) * Dd + i * HIDc]) =
        make_uint2(*reinterpret_cast<unsigned*>(&a), *reinterpret_cast<unsigned*>(&b));
}

// GAT for batches 1..7: self-loop only => s = x. Writes fp16.
__global__ void k_gat_rest(const float* __restrict__ x, const float* __restrict__ W,
                           const float* __restrict__ bias) {
    int idx = blockIdx.x * 256 + threadIdx.x;
    if (idx >= Tt * (Bb - 1) * Nn) return;
    int t = idx / ((Bb - 1) * Nn);
    int r = idx - t * (Bb - 1) * Nn;
    int b = 1 + (r >> 9);
    int n = r & (Nn - 1);
    float xi = x[((size_t)b * Tt + t) * Nn + n];
    float gg[4];
#pragma unroll
    for (int k = 0; k < HIDc; k++) {
        float g = fmaf(xi, W[k], bias[k]);
        gg[k] = g > 0.f ? g : 0.f;
    }
    __half2 a = __floats2half2_rn(gg[0], gg[1]);
    __half2 bh = __floats2half2_rn(gg[2], gg[3]);
    *(uint2*)(&g_seq16[(size_t)(t * Bb + b) * Dd + n * HIDc]) =
        make_uint2(*reinterpret_cast<unsigned*>(&a), *reinterpret_cast<unsigned*>(&bh));
}

// ---------------- input GEMM on HMMA: Z^T[8192,1024] = w_ih @ seq^T + bias ----------------
#define BROW 40
__global__ void __launch_bounds__(512, 1)
k_zxt(const float* __restrict__ bih, const float* __restrict__ bhh) {
    __shared__ __align__(16) __half Bs[2][256 * BROW];
    int tid = threadIdx.x;
    int wi = tid >> 5;
    int lane = tid & 31;
    int wm = wi >> 2;
    int wn = wi & 3;
    int bm = blockIdx.y * 128;
    int bn = blockIdx.x * 256;

    int li0 = tid * 2;
    int row0 = li0 >> 2, c0 = li0 & 3;
    int li1 = li0 + 1;
    int row1 = li1 >> 2, c1 = li1 & 3;
    const __half* src0 = g_seq16 + (size_t)(bn + row0) * Dd + c0 * 8;
    const __half* src1 = g_seq16 + (size_t)(bn + row1) * Dd + c1 * 8;
    unsigned dst0 = smem_u32(&Bs[0][row0 * BROW + c0 * 8]);
    unsigned dst1 = smem_u32(&Bs[0][row1 * BROW + c1 * 8]);
    const unsigned bufB = 256 * BROW * 2;

    const uint4* Ap = ((const uint4*)g_wpk2) + ((size_t)(bm / 16 + wm * 2) * 128) * 32 + lane;
    int bfrag = (wn * 64 + (lane >> 2)) * BROW + (lane & 3) * 2;

    float acc[2][8][4];
#pragma unroll
    for (int a = 0; a < 2; a++)
#pragma unroll
        for (int b = 0; b < 8; b++)
#pragma unroll
            for (int c = 0; c < 4; c++) acc[a][b][c] = 0.f;

    asm volatile("cp.async.cg.shared.global [%0], [%1], 16;" :: "r"(dst0), "l"(src0));
    asm volatile("cp.async.cg.shared.global [%0], [%1], 16;" :: "r"(dst1), "l"(src1));
    asm volatile("cp.async.commit_group;");

    for (int kt = 0; kt < 64; kt++) {
        int buf = kt & 1;
        if (kt + 1 < 64) {
            unsigned off = ((kt + 1) & 1) * bufB;
            asm volatile("cp.async.cg.shared.global [%0], [%1], 16;"
                         :: "r"(dst0 + off), "l"(src0 + (kt + 1) * 32));
            asm volatile("cp.async.cg.shared.global [%0], [%1], 16;"
                         :: "r"(dst1 + off), "l"(src1 + (kt + 1) * 32));
            asm volatile("cp.async.commit_group;");
            asm volatile("cp.async.wait_group 1;");
        } else {
            asm volatile("cp.async.wait_group 0;");
        }
        __syncthreads();

        const __half* Bb_ = &Bs[buf][bfrag];
#pragma unroll
        for (int kk = 0; kk < 2; kk++) {
            int kc = kt * 2 + kk;
            uint4 a0 = Ap[(size_t)(0 * 128 + kc) * 32];
            uint4 a1 = Ap[(size_t)(1 * 128 + kc) * 32];
#pragma unroll
            for (int nt = 0; nt < 8; nt++) {
                unsigned b0 = *(const unsigned*)(Bb_ + nt * 8 * BROW + kk * 16);
                unsigned b1 = *(const unsigned*)(Bb_ + nt * 8 * BROW + kk * 16 + 8);
                asm volatile(
                    "mma.sync.aligned.m16n8k16.row.col.f32.f16.f16.f32 "
                    "{%0,%1,%2,%3}, {%4,%5,%6,%7}, {%8,%9}, {%0,%1,%2,%3};"
                    : "+f"(acc[0][nt][0]), "+f"(acc[0][nt][1]),
                      "+f"(acc[0][nt][2]), "+f"(acc[0][nt][3])
                    : "r"(a0.x), "r"(a0.y), "r"(a0.z), "r"(a0.w), "r"(b0), "r"(b1));
                asm volatile(
                    "mma.sync.aligned.m16n8k16.row.col.f32.f16.f16.f32 "
                    "{%0,%1,%2,%3}, {%4,%5,%6,%7}, {%8,%9}, {%0,%1,%2,%3};"
                    : "+f"(acc[1][nt][0]), "+f"(acc[1][nt][1]),
                      "+f"(acc[1][nt][2]), "+f"(acc[1][nt][3])
                    : "r"(a1.x), "r"(a1.y), "r"(a1.z), "r"(a1.w), "r"(b0), "r"(b1));
            }
        }
        __syncthreads();
    }

#pragma unroll
    for (int mtl = 0; mtl < 2; mtl++) {
        int m = bm + wm * 32 + mtl * 16 + (lane >> 2);
        float bA = bih[m] + bhh[m];
        float bB = bih[m + 8] + bhh[m + 8];
#pragma unroll
        for (int nt = 0; nt < 8; nt++) {
            int n = bn + wn * 64 + nt * 8 + (lane & 3) * 2;
            *(float2*)(&g_zxt[(size_t)m * 1024 + n]) =
                make_float2(acc[mtl][nt][0] + bA, acc[mtl][nt][1] + bA);
            *(float2*)(&g_zxt[(size_t)(m + 8) * 1024 + n]) =
                make_float2(acc[mtl][nt][2] + bB, acc[mtl][nt][3] + bB);
        }
    }
}

// ---------------- persistent LSTM: weights in REGISTERS + SMEM (zero L2 per step) ----------------
__global__ void __launch_bounds__(512, 1)
k_lstm(const float* __restrict__ wlin, const float* __restrict__ blin,
       float* __restrict__ out) {
    extern __shared__ __align__(16) char smem[];
    __half* h_h = (__half*)(smem + SM_HH);
    float*  fr  = (float*)(smem + SM_FR);
    float*  cs_ = (float*)(smem + SM_CS);
    uint4*  ws  = (uint4*)(smem + SM_WS);

    int tid = threadIdx.x;
    int wi = tid >> 5;
    int lane = tid & 31;
    int bid = blockIdx.x;
    int d0 = bid * 16;
    int ks = wi & 3;
    int mi = wi >> 2;
    const uint4* Abase = ((const uint4*)g_wpk) + ((size_t)(bid * 16 + mi * 4 + ks) * 32) * 32;
    int k0base = ks * 512;
    const __half* hb = &h_h[(lane >> 2) * HROW];
    uint4* wsw = ws + wi * (NCACHE * 32);

    int dd2 = tid >> 3;
    int bb = tid & 7;
    const float* zxb = g_zxt + (size_t)(d0 + dd2) * 1024 + bb;

    // pin NGLOB chunks in registers (step-invariant), NCACHE chunks in smem
    uint4 wreg[NGLOB];
#pragma unroll
    for (int ci = 0; ci < NGLOB; ci++)
        wreg[ci] = Abase[(NCACHE + ci) * 32 + lane];
#pragma unroll
    for (int ch = 0; ch < NCACHE; ch++)
        wsw[ch * 32 + lane] = Abase[ch * 32 + lane];
    for (int u = tid; u < Bb * HROW / 8; u += 512)
        ((uint4*)h_h)[u] = make_uint4(0, 0, 0, 0);
    if (tid < 128) cs_[tid] = 0.f;
    __syncthreads();

    for (int t = 0; t < Tt; t++) {
        float zpre[4];
        if (tid < 128) {
            const float* zp = zxb + t * Bb;
#pragma unroll
            for (int g4 = 0; g4 < 4; g4++) zpre[g4] = zp[(size_t)g4 * 2097152];
        }

        if (t > 0) {
            const __half* hin = g_h16[t & 1];
#pragma unroll
            for (int u = 0; u < 4; u++) {
                int i = tid + u * 512;
                int b = i >> 8, k8 = i & 255;
                uint4 v = *(const uint4*)(hin + ((size_t)b << 11) + k8 * 8);
                *(uint4*)(&h_h[b * HROW + k8 * 8]) = v;
            }
            __syncthreads();
        }

        float c0 = 0.f, c1 = 0.f, c2 = 0.f, c3 = 0.f;
        // register-pinned chunks first (no memory wait at all)
#pragma unroll
        for (int ci = 0; ci < NGLOB; ci++) {
            int ch = NCACHE + ci;
            uint4 a = wreg[ci];
            int k = k0base + ch * 16 + (lane & 3) * 2;
            unsigned b0 = *(const unsigned*)(hb + k);
            unsigned b1 = *(const unsigned*)(hb + k + 8);
            asm volatile(
                "mma.sync.aligned.m16n8k16.row.col.f32.f16.f16.f32 "
                "{%0,%1,%2,%3}, {%4,%5,%6,%7}, {%8,%9}, {%0,%1,%2,%3};"
                : "+f"(c0), "+f"(c1), "+f"(c2), "+f"(c3)
                : "r"(a.x), "r"(a.y), "r"(a.z), "r"(a.w), "r"(b0), "r"(b1));
        }
        // smem-cached chunks
#pragma unroll
        for (int ch = 0; ch < NCACHE; ch++) {
            uint4 a = wsw[ch * 32 + lane];
            int k = k0base + ch * 16 + (lane & 3) * 2;
            unsigned b0 = *(const unsigned*)(hb + k);
            unsigned b1 = *(const unsigned*)(hb + k + 8);
            asm volatile(
                "mma.sync.aligned.m16n8k16.row.col.f32.f16.f16.f32 "
                "{%0,%1,%2,%3}, {%4,%5,%6,%7}, {%8,%9}, {%0,%1,%2,%3};"
                : "+f"(c0), "+f"(c1), "+f"(c2), "+f"(c3)
                : "r"(a.x), "r"(a.y), "r"(a.z), "r"(a.w), "r"(b0), "r"(b1));
        }
        *(float4*)(&fr[((ks * 4 + mi) * 32 + lane) * 4]) = make_float4(c0, c1, c2, c3);
        __syncthreads();

        if (tid < 128) {
            int li = (dd2 & 7) * 4 + (bb >> 1);
            int ri = (bb & 1) + ((dd2 >> 3) << 1);
            float z[4];
#pragma unroll
            for (int g4 = 0; g4 < 4; g4++) {
                float s = zpre[g4];
#pragma unroll
                for (int kss = 0; kss < 4; kss++)
                    s += fr[((kss * 4 + g4) * 32 + li) * 4 + ri];
                z[g4] = s;
            }
            float ig = 1.f / (1.f + expf(-z[0]));
            float fg = 1.f / (1.f + expf(-z[1]));
            float gg = tanhf(z[2]);
            float og = 1.f / (1.f + expf(-z[3]));
            float cn = fg * cs_[bb * 16 + dd2] + ig * gg;
            cs_[bb * 16 + dd2] = cn;
            float hn = og * tanhf(cn);
            int par = (t + 1) & 1;
            g_h16[par][bb * Dd + d0 + dd2] = __float2half(hn);
            g_h[par][bb * Dd + d0 + dd2] = hn;
        }
        __syncthreads();

        // grid barrier: single counter, release-arrive + acquire-poll (proven best)
        if (tid == 0) {
            int* bar = &g_bar[t];
            asm volatile("red.release.gpu.add.u32 [%0], 1;" :: "l"(bar) : "memory");
            unsigned v;
            do {
                asm volatile("ld.acquire.gpu.u32 %0, [%1];" : "=r"(v) : "l"(bar) : "memory");
            } while (v < 128);
        }
        __syncthreads();
    }

    // final linear: h_T in g_h[0]
    {
        int col = bid * 4 + (wi & 3);
        int p = wi >> 2;
        const float* wl = wlin + (size_t)col * Dd + lane * 4;
        const float* h0 = g_h[0] + (size_t)(2 * p) * Dd + lane * 4;
        const float* h1 = g_h[0] + (size_t)(2 * p + 1) * Dd + lane * 4;
        ull s0 = 0ull, s1 = 0ull;
#pragma unroll 4
        for (int it = 0; it < 16; it++) {
            int ko = it * 128;
            ulonglong2 wv = *(const ulonglong2*)(wl + ko);
            ulonglong2 hv0 = *(const ulonglong2*)(h0 + ko);
            ulonglong2 hv1 = *(const ulonglong2*)(h1 + ko);
            ffma2(s0, wv.x, hv0.x);
            ffma2(s0, wv.y, hv0.y);
            ffma2(s1, wv.x, hv1.x);
            ffma2(s1, wv.y, hv1.y);
        }
        float f0 = fsum2(s0), f1 = fsum2(s1);
#pragma unroll
        for (int d = 16; d; d >>= 1) {
            f0 += __shfl_xor_sync(0xffffffffu, f0, d);
            f1 += __shfl_xor_sync(0xffffffffu, f1, d);
        }
        if (lane == 0) {
            float bl = blin[col];
            out[(2 * p) * Nn + col]     = f0 + bl;
            out[(2 * p + 1) * Nn + col] = f1 + bl;
        }
    }
}

// ---------------- launch: fork-join so weight packing overlaps GAT/zxt ----------------
extern "C" void kernel_launch(void* const* d_in, const int* in_sizes, int n_in,
                              void* d_out, int out_size) {
    const float* x    = (const float*)d_in[0];
    const float* gw   = (const float*)d_in[1];
    const float* as_  = (const float*)d_in[2];
    const float* ad_  = (const float*)d_in[3];
    const float* gb   = (const float*)d_in[4];
    const float* wih  = (const float*)d_in[5];
    const float* whh  = (const float*)d_in[6];
    const float* bih  = (const float*)d_in[7];
    const float* bhh  = (const float*)d_in[8];
    const float* wlin = (const float*)d_in[9];
    const float* blin = (const float*)d_in[10];
    const int*   ei   = (const int*)d_in[11];
    (void)in_sizes; (void)n_in; (void)out_size;

    static int inited = 0;
    static cudaStream_t s2;
    static cudaEvent_t ev_fork, ev_wih, ev_whh;
    if (!inited) {
        cudaFuncSetAttribute(k_lstm, cudaFuncAttributeMaxDynamicSharedMemorySize, SM_TOTAL);
        cudaStreamCreateWithFlags(&s2, cudaStreamNonBlocking);
        cudaEventCreateWithFlags(&ev_fork, cudaEventDisableTiming);
        cudaEventCreateWithFlags(&ev_wih, cudaEventDisableTiming);
        cudaEventCreateWithFlags(&ev_whh, cudaEventDisableTiming);
        inited = 1;
    }

    // fork: side stream packs weights while main stream does graph + GAT
    cudaEventRecord(ev_fork, 0);
    cudaStreamWaitEvent(s2, ev_fork, 0);
    k_wcvt_ih<<<4096, 512, 0, s2>>>(wih);
    cudaEventRecord(ev_wih, s2);
    k_wcvt_hh<<<4096, 512, 0, s2>>>(whh);
    cudaEventRecord(ev_whh, s2);

    // main stream: CSR build + GAT (independent of weight packing)
    k_graph<<<1, 512>>>(ei, gw, as_, ad_);
    k_gat_b0<<<Tt, Nn>>>(x, gw, gb);
    k_gat_rest<<<1792, 256>>>(x, gw, gb);

    // zxt needs packed w_ih
    cudaStreamWaitEvent(0, ev_wih, 0);
    {
        dim3 grid(4, 64);
        k_zxt<<<grid, 512>>>(bih, bhh);
    }

    // lstm needs packed w_hh
    cudaStreamWaitEvent(0, ev_whh, 0);
    k_lstm<<<128, 512, SM_TOTAL>>>(wlin, blin, (float*)d_out);
}

// round 17
// speedup vs baseline: 2.4460x; 1.0367x over previous
#include <cuda_runtime.h>
#include <cuda_fp16.h>
#include <math.h>

// Problem constants
#define Bb   8
#define Tt   128
#define Nn   512
#define HIDc 4
#define Dd   2048
#define Ee   16384
#define FD   8192
#define NEG  0.2f

// k_lstm smem layout (dynamic, opt-in)
#define HROW   2056
#define NCACHE 18                     // k-chunks cached in smem
#define NGLOB  (32 - NCACHE)          // k-chunks pinned in REGISTERS (14 => 56 regs)
#define SM_HH    0
#define SM_FR    32896                // 8*2056*2
#define SM_CS    (SM_FR + 8192)
#define SM_WS    (SM_CS + 512)        // 41600, 16B aligned
#define SM_TOTAL (SM_WS + 16 * NCACHE * 32 * 16)   // + 144 KB = 189056

// ---------------- device scratch (no allocations allowed) ----------------
__device__ __align__(256) __half g_seq16[1024 * 2048];  // [T*B, D] GAT out fp16, 4 MB
__device__ __align__(256) float g_zxt[8192u * 1024u];   // Z^T [4D, T*B], 32 MB
__device__ __align__(256) unsigned g_wpk[8388608];      // w_hh packed A-frags, 32 MB
__device__ __align__(256) unsigned g_wpk2[8388608];     // w_ih packed A-frags, 32 MB
__device__ __align__(256) float  g_h[Bb * Dd];          // fp32 h_T (final linear only)
__device__ __align__(256) __half g_h16[2][Bb * Dd];     // fp16 hidden (mma B operand)
__device__ int   g_bar[Tt];
__device__ int   g_deg[Nn];
__device__ int   g_off[Nn];
__device__ int   g_csr[Ee];
__device__ float g_cs, g_cd;

// ---------------- helpers ----------------
typedef unsigned long long ull;

__device__ __forceinline__ ull pk2(float x, float y) {
    ull r;
    asm("mov.b64 %0, {%1, %2};" : "=l"(r) : "f"(x), "f"(y));
    return r;
}
__device__ __forceinline__ void ffma2(ull &d, ull a, ull b) {
    asm("fma.rn.f32x2 %0, %1, %2, %0;" : "+l"(d) : "l"(a), "l"(b));
}
__device__ __forceinline__ float fsum2(ull v) {
    float x, y;
    asm("mov.b64 {%0, %1}, %2;" : "=f"(x), "=f"(y) : "l"(v));
    return x + y;
}
__device__ __forceinline__ unsigned smem_u32(const void* p) {
    unsigned a;
    asm("{ .reg .u64 t; cvta.to.shared.u64 t, %1; cvt.u32.u64 %0, t; }"
        : "=r"(a) : "l"(p));
    return a;
}

// ---------------- w_hh fp32 -> fp16 packed m16n8k16 A-frag order ----------------
__global__ void k_wcvt_hh(const float* __restrict__ whh) {
    unsigned idx = blockIdx.x * 512 + threadIdx.x;
    if (idx >= 2097152u) return;
    unsigned lane  = idx & 31;
    unsigned ch    = (idx >> 5) & 31;
    unsigned outer = idx >> 10;
    unsigned ks  = outer & 3;
    unsigned mi  = (outer >> 2) & 3;
    unsigned bid = outer >> 4;
    unsigned rbase = mi * Dd + bid * 16 + (lane >> 2);
    unsigned kbase = ks * 512 + ch * 16 + (lane & 3) * 2;
    unsigned r[4];
#pragma unroll
    for (int rr = 0; rr < 4; rr++) {
        unsigned row = rbase + (rr & 1) * 8;
        unsigned k   = kbase + ((rr >> 1) & 1) * 8;
        float2 v = *(const float2*)(whh + (size_t)row * Dd + k);
        __half2 h = __floats2half2_rn(v.x, v.y);
        r[rr] = *reinterpret_cast<unsigned*>(&h);
    }
    ((uint4*)g_wpk)[idx] = make_uint4(r[0], r[1], r[2], r[3]);
}

// ---------------- w_ih fp32 -> fp16 packed A-frag order ----------------
__global__ void k_wcvt_ih(const float* __restrict__ wih) {
    unsigned idx = blockIdx.x * 512 + threadIdx.x;
    if (idx >= 2097152u) return;
    unsigned lane = idx & 31;
    unsigned kc   = (idx >> 5) & 127;
    unsigned mt   = idx >> 12;
    unsigned rbase = mt * 16 + (lane >> 2);
    unsigned kbase = kc * 16 + (lane & 3) * 2;
    unsigned r[4];
#pragma unroll
    for (int rr = 0; rr < 4; rr++) {
        unsigned row = rbase + (rr & 1) * 8;
        unsigned k   = kbase + ((rr >> 1) & 1) * 8;
        float2 v = *(const float2*)(wih + (size_t)row * Dd + k);
        __half2 h = __floats2half2_rn(v.x, v.y);
        r[rr] = *reinterpret_cast<unsigned*>(&h);
    }
    ((uint4*)g_wpk2)[idx] = make_uint4(r[0], r[1], r[2], r[3]);
}

// ---------------- fused CSR build: consts + degree + scan + fill (1 block) ----------------
__global__ void __launch_bounds__(512)
k_graph(const int* __restrict__ ei, const float* __restrict__ W,
        const float* __restrict__ as_, const float* __restrict__ ad_) {
    __shared__ int sdeg[Nn];
    __shared__ int s[Nn];
    __shared__ int scur[Nn];
    int tid = threadIdx.x;
    if (tid == 0) {
        float cs = 0.f, cd = 0.f;
        for (int k = 0; k < HIDc; k++) { cs += W[k] * as_[k]; cd += W[k] * ad_[k]; }
        g_cs = cs; g_cd = cd;
    }
    sdeg[tid] = 0;
    if (tid < Tt) g_bar[tid] = 0;
    __syncthreads();
    for (int e = tid; e < Ee; e += 512) atomicAdd(&sdeg[ei[Ee + e]], 1);
    __syncthreads();
    int d = sdeg[tid];
    s[tid] = d;
    __syncthreads();
    for (int off = 1; off < Nn; off <<= 1) {
        int t = 0;
        if (tid >= off) t = s[tid - off];
        __syncthreads();
        s[tid] += t;
        __syncthreads();
    }
    g_deg[tid] = d;
    g_off[tid] = s[tid] - d;
    scur[tid] = s[tid] - d;
    __syncthreads();
    for (int e = tid; e < Ee; e += 512) {
        int src = ei[e];
        int dst = ei[Ee + e];
        int pos = atomicAdd(&scur[dst], 1);
        g_csr[pos] = src;
    }
}

// GAT for batch-0 nodes. One block per t. Writes fp16.
__global__ void k_gat_b0(const float* __restrict__ x, const float* __restrict__ W,
                         const float* __restrict__ bias) {
    __shared__ float xs[Nn];
    int t = blockIdx.x;
    int i = threadIdx.x;
    xs[i] = x[t * Nn + i];
    __syncthreads();
    float cs = g_cs, cd = g_cd;
    float xi = xs[i];
    float es = xi * (cs + cd);
    es = es > 0.f ? es : NEG * es;
    int beg = g_off[i], end = beg + g_deg[i];
    float m = es;
    for (int e = beg; e < end; e++) {
        float v = cs * xs[g_csr[e]] + cd * xi;
        v = v > 0.f ? v : NEG * v;
        m = fmaxf(m, v);
    }
    float den = expf(es - m);
    float ssum = den * xi;
    for (int e = beg; e < end; e++) {
        float xsrc = xs[g_csr[e]];
        float v = cs * xsrc + cd * xi;
        v = v > 0.f ? v : NEG * v;
        float w = expf(v - m);
        den += w;
        ssum += w * xsrc;
    }
    float sA = ssum / den;
    float gg[4];
#pragma unroll
    for (int k = 0; k < HIDc; k++) {
        float g = fmaf(sA, W[k], bias[k]);
        gg[k] = g > 0.f ? g : 0.f;
    }
    __half2 a = __floats2half2_rn(gg[0], gg[1]);
    __half2 b = __floats2half2_rn(gg[2], gg[3]);
    *(uint2*)(&g_seq16[(size_t)(t * Bb) * Dd + i * HIDc]) =
        make_uint2(*reinterpret_cast<unsigned*>(&a), *reinterpret_cast<unsigned*>(&b));
}

// GAT for batches 1..7: self-loop only => s = x. Writes fp16.
__global__ void k_gat_rest(const float* __restrict__ x, const float* __restrict__ W,
                           const float* __restrict__ bias) {
    int idx = blockIdx.x * 256 + threadIdx.x;
    if (idx >= Tt * (Bb - 1) * Nn) return;
    int t = idx / ((Bb - 1) * Nn);
    int r = idx - t * (Bb - 1) * Nn;
    int b = 1 + (r >> 9);
    int n = r & (Nn - 1);
    float xi = x[((size_t)b * Tt + t) * Nn + n];
    float gg[4];
#pragma unroll
    for (int k = 0; k < HIDc; k++) {
        float g = fmaf(xi, W[k], bias[k]);
        gg[k] = g > 0.f ? g : 0.f;
    }
    __half2 a = __floats2half2_rn(gg[0], gg[1]);
    __half2 bh = __floats2half2_rn(gg[2], gg[3]);
    *(uint2*)(&g_seq16[(size_t)(t * Bb + b) * Dd + n * HIDc]) =
        make_uint2(*reinterpret_cast<unsigned*>(&a), *reinterpret_cast<unsigned*>(&bh));
}

// ---------------- input GEMM on HMMA: Z^T[8192,1024] = w_ih @ seq^T + bias ----------------
#define BROW 40
__global__ void __launch_bounds__(512, 1)
k_zxt(const float* __restrict__ bih, const float* __restrict__ bhh) {
    __shared__ __align__(16) __half Bs[2][256 * BROW];
    int tid = threadIdx.x;
    int wi = tid >> 5;
    int lane = tid & 31;
    int wm = wi >> 2;
    int wn = wi & 3;
    int bm = blockIdx.y * 128;
    int bn = blockIdx.x * 256;

    int li0 = tid * 2;
    int row0 = li0 >> 2, c0 = li0 & 3;
    int li1 = li0 + 1;
    int row1 = li1 >> 2, c1 = li1 & 3;
    const __half* src0 = g_seq16 + (size_t)(bn + row0) * Dd + c0 * 8;
    const __half* src1 = g_seq16 + (size_t)(bn + row1) * Dd + c1 * 8;
    unsigned dst0 = smem_u32(&Bs[0][row0 * BROW + c0 * 8]);
    unsigned dst1 = smem_u32(&Bs[0][row1 * BROW + c1 * 8]);
    const unsigned bufB = 256 * BROW * 2;

    const uint4* Ap = ((const uint4*)g_wpk2) + ((size_t)(bm / 16 + wm * 2) * 128) * 32 + lane;
    int bfrag = (wn * 64 + (lane >> 2)) * BROW + (lane & 3) * 2;

    float acc[2][8][4];
#pragma unroll
    for (int a = 0; a < 2; a++)
#pragma unroll
        for (int b = 0; b < 8; b++)
#pragma unroll
            for (int c = 0; c < 4; c++) acc[a][b][c] = 0.f;

    asm volatile("cp.async.cg.shared.global [%0], [%1], 16;" :: "r"(dst0), "l"(src0));
    asm volatile("cp.async.cg.shared.global [%0], [%1], 16;" :: "r"(dst1), "l"(src1));
    asm volatile("cp.async.commit_group;");

    for (int kt = 0; kt < 64; kt++) {
        int buf = kt & 1;
        if (kt + 1 < 64) {
            unsigned off = ((kt + 1) & 1) * bufB;
            asm volatile("cp.async.cg.shared.global [%0], [%1], 16;"
                         :: "r"(dst0 + off), "l"(src0 + (kt + 1) * 32));
            asm volatile("cp.async.cg.shared.global [%0], [%1], 16;"
                         :: "r"(dst1 + off), "l"(src1 + (kt + 1) * 32));
            asm volatile("cp.async.commit_group;");
            asm volatile("cp.async.wait_group 1;");
        } else {
            asm volatile("cp.async.wait_group 0;");
        }
        __syncthreads();

        const __half* Bb_ = &Bs[buf][bfrag];
#pragma unroll
        for (int kk = 0; kk < 2; kk++) {
            int kc = kt * 2 + kk;
            uint4 a0 = Ap[(size_t)(0 * 128 + kc) * 32];
            uint4 a1 = Ap[(size_t)(1 * 128 + kc) * 32];
#pragma unroll
            for (int nt = 0; nt < 8; nt++) {
                unsigned b0 = *(const unsigned*)(Bb_ + nt * 8 * BROW + kk * 16);
                unsigned b1 = *(const unsigned*)(Bb_ + nt * 8 * BROW + kk * 16 + 8);
                asm volatile(
                    "mma.sync.aligned.m16n8k16.row.col.f32.f16.f16.f32 "
                    "{%0,%1,%2,%3}, {%4,%5,%6,%7}, {%8,%9}, {%0,%1,%2,%3};"
                    : "+f"(acc[0][nt][0]), "+f"(acc[0][nt][1]),
                      "+f"(acc[0][nt][2]), "+f"(acc[0][nt][3])
                    : "r"(a0.x), "r"(a0.y), "r"(a0.z), "r"(a0.w), "r"(b0), "r"(b1));
                asm volatile(
                    "mma.sync.aligned.m16n8k16.row.col.f32.f16.f16.f32 "
                    "{%0,%1,%2,%3}, {%4,%5,%6,%7}, {%8,%9}, {%0,%1,%2,%3};"
                    : "+f"(acc[1][nt][0]), "+f"(acc[1][nt][1]),
                      "+f"(acc[1][nt][2]), "+f"(acc[1][nt][3])
                    : "r"(a1.x), "r"(a1.y), "r"(a1.z), "r"(a1.w), "r"(b0), "r"(b1));
            }
        }
        __syncthreads();
    }

#pragma unroll
    for (int mtl = 0; mtl < 2; mtl++) {
        int m = bm + wm * 32 + mtl * 16 + (lane >> 2);
        float bA = bih[m] + bhh[m];
        float bB = bih[m + 8] + bhh[m + 8];
#pragma unroll
        for (int nt = 0; nt < 8; nt++) {
            int n = bn + wn * 64 + nt * 8 + (lane & 3) * 2;
            *(float2*)(&g_zxt[(size_t)m * 1024 + n]) =
                make_float2(acc[mtl][nt][0] + bA, acc[mtl][nt][1] + bA);
            *(float2*)(&g_zxt[(size_t)(m + 8) * 1024 + n]) =
                make_float2(acc[mtl][nt][2] + bB, acc[mtl][nt][3] + bB);
        }
    }
}

// ---------------- persistent LSTM: 14 reg chunks + 18 smem chunks ----------------
__global__ void __launch_bounds__(512, 1)
k_lstm(const float* __restrict__ wlin, const float* __restrict__ blin,
       float* __restrict__ out) {
    extern __shared__ __align__(16) char smem[];
    __half* h_h = (__half*)(smem + SM_HH);
    float*  fr  = (float*)(smem + SM_FR);
    float*  cs_ = (float*)(smem + SM_CS);
    uint4*  ws  = (uint4*)(smem + SM_WS);

    int tid = threadIdx.x;
    int wi = tid >> 5;
    int lane = tid & 31;
    int bid = blockIdx.x;
    int d0 = bid * 16;
    int ks = wi & 3;
    int mi = wi >> 2;
    const uint4* Abase = ((const uint4*)g_wpk) + ((size_t)(bid * 16 + mi * 4 + ks) * 32) * 32;
    int k0base = ks * 512;
    const __half* hb = &h_h[(lane >> 2) * HROW];
    uint4* wsw = ws + wi * (NCACHE * 32);

    int dd2 = tid >> 3;
    int bb = tid & 7;
    const float* zxb = g_zxt + (size_t)(d0 + dd2) * 1024 + bb;

    // pin NGLOB chunks in registers (step-invariant), NCACHE chunks in smem
    uint4 wreg[NGLOB];
#pragma unroll
    for (int ci = 0; ci < NGLOB; ci++)
        wreg[ci] = Abase[(NCACHE + ci) * 32 + lane];
#pragma unroll
    for (int ch = 0; ch < NCACHE; ch++)
        wsw[ch * 32 + lane] = Abase[ch * 32 + lane];
    for (int u = tid; u < Bb * HROW / 8; u += 512)
        ((uint4*)h_h)[u] = make_uint4(0, 0, 0, 0);
    if (tid < 128) cs_[tid] = 0.f;
    __syncthreads();

    for (int t = 0; t < Tt; t++) {
        float zpre[4];
        if (tid < 128) {
            const float* zp = zxb + t * Bb;
#pragma unroll
            for (int g4 = 0; g4 < 4; g4++) zpre[g4] = zp[(size_t)g4 * 2097152];
        }

        if (t > 0) {
            const __half* hin = g_h16[t & 1];
#pragma unroll
            for (int u = 0; u < 4; u++) {
                int i = tid + u * 512;
                int b = i >> 8, k8 = i & 255;
                uint4 v = *(const uint4*)(hin + ((size_t)b << 11) + k8 * 8);
                *(uint4*)(&h_h[b * HROW + k8 * 8]) = v;
            }
            __syncthreads();
        }

        float c0 = 0.f, c1 = 0.f, c2 = 0.f, c3 = 0.f;
        // register-pinned chunks first (no memory wait)
#pragma unroll
        for (int ci = 0; ci < NGLOB; ci++) {
            int ch = NCACHE + ci;
            uint4 a = wreg[ci];
            int k = k0base + ch * 16 + (lane & 3) * 2;
            unsigned b0 = *(const unsigned*)(hb + k);
            unsigned b1 = *(const unsigned*)(hb + k + 8);
            asm volatile(
                "mma.sync.aligned.m16n8k16.row.col.f32.f16.f16.f32 "
                "{%0,%1,%2,%3}, {%4,%5,%6,%7}, {%8,%9}, {%0,%1,%2,%3};"
                : "+f"(c0), "+f"(c1), "+f"(c2), "+f"(c3)
                : "r"(a.x), "r"(a.y), "r"(a.z), "r"(a.w), "r"(b0), "r"(b1));
        }
        // smem-cached chunks
#pragma unroll
        for (int ch = 0; ch < NCACHE; ch++) {
            uint4 a = wsw[ch * 32 + lane];
            int k = k0base + ch * 16 + (lane & 3) * 2;
            unsigned b0 = *(const unsigned*)(hb + k);
            unsigned b1 = *(const unsigned*)(hb + k + 8);
            asm volatile(
                "mma.sync.aligned.m16n8k16.row.col.f32.f16.f16.f32 "
                "{%0,%1,%2,%3}, {%4,%5,%6,%7}, {%8,%9}, {%0,%1,%2,%3};"
                : "+f"(c0), "+f"(c1), "+f"(c2), "+f"(c3)
                : "r"(a.x), "r"(a.y), "r"(a.z), "r"(a.w), "r"(b0), "r"(b1));
        }
        *(float4*)(&fr[((ks * 4 + mi) * 32 + lane) * 4]) = make_float4(c0, c1, c2, c3);
        __syncthreads();

        if (tid < 128) {
            int li = (dd2 & 7) * 4 + (bb >> 1);
            int ri = (bb & 1) + ((dd2 >> 3) << 1);
            float z[4];
#pragma unroll
            for (int g4 = 0; g4 < 4; g4++) {
                float s = zpre[g4];
#pragma unroll
                for (int kss = 0; kss < 4; kss++)
                    s += fr[((kss * 4 + g4) * 32 + li) * 4 + ri];
                z[g4] = s;
            }
            float ig = 1.f / (1.f + expf(-z[0]));
            float fg = 1.f / (1.f + expf(-z[1]));
            float gg = tanhf(z[2]);
            float og = 1.f / (1.f + expf(-z[3]));
            float cn = fg * cs_[bb * 16 + dd2] + ig * gg;
            cs_[bb * 16 + dd2] = cn;
            float hn = og * tanhf(cn);
            g_h16[(t + 1) & 1][bb * Dd + d0 + dd2] = __float2half(hn);
            if (t == Tt - 1) g_h[bb * Dd + d0 + dd2] = hn;   // only final h needed in fp32
        }
        __syncthreads();

        // grid barrier: single counter, release-arrive + acquire-poll (proven best)
        if (tid == 0) {
            int* bar = &g_bar[t];
            asm volatile("red.release.gpu.add.u32 [%0], 1;" :: "l"(bar) : "memory");
            unsigned v;
            do {
                asm volatile("ld.acquire.gpu.u32 %0, [%1];" : "=r"(v) : "l"(bar) : "memory");
            } while (v < 128);
        }
        __syncthreads();
    }

    // final linear: h_T in g_h
    {
        int col = bid * 4 + (wi & 3);
        int p = wi >> 2;
        const float* wl = wlin + (size_t)col * Dd + lane * 4;
        const float* h0 = g_h + (size_t)(2 * p) * Dd + lane * 4;
        const float* h1 = g_h + (size_t)(2 * p + 1) * Dd + lane * 4;
        ull s0 = 0ull, s1 = 0ull;
#pragma unroll 4
        for (int it = 0; it < 16; it++) {
            int ko = it * 128;
            ulonglong2 wv = *(const ulonglong2*)(wl + ko);
            ulonglong2 hv0 = *(const ulonglong2*)(h0 + ko);
            ulonglong2 hv1 = *(const ulonglong2*)(h1 + ko);
            ffma2(s0, wv.x, hv0.x);
            ffma2(s0, wv.y, hv0.y);
            ffma2(s1, wv.x, hv1.x);
            ffma2(s1, wv.y, hv1.y);
        }
        float f0 = fsum2(s0), f1 = fsum2(s1);
#pragma unroll
        for (int d = 16; d; d >>= 1) {
            f0 += __shfl_xor_sync(0xffffffffu, f0, d);
            f1 += __shfl_xor_sync(0xffffffffu, f1, d);
        }
        if (lane == 0) {
            float bl = blin[col];
            out[(2 * p) * Nn + col]     = f0 + bl;
            out[(2 * p + 1) * Nn + col] = f1 + bl;
        }
    }
}

// ---------------- launch: fork-join so weight packing overlaps GAT/zxt ----------------
extern "C" void kernel_launch(void* const* d_in, const int* in_sizes, int n_in,
                              void* d_out, int out_size) {
    const float* x    = (const float*)d_in[0];
    const float* gw   = (const float*)d_in[1];
    const float* as_  = (const float*)d_in[2];
    const float* ad_  = (const float*)d_in[3];
    const float* gb   = (const float*)d_in[4];
    const float* wih  = (const float*)d_in[5];
    const float* whh  = (const float*)d_in[6];
    const float* bih  = (const float*)d_in[7];
    const float* bhh  = (const float*)d_in[8];
    const float* wlin = (const float*)d_in[9];
    const float* blin = (const float*)d_in[10];
    const int*   ei   = (const int*)d_in[11];
    (void)in_sizes; (void)n_in; (void)out_size;

    static int inited = 0;
    static cudaStream_t s2;
    static cudaEvent_t ev_fork, ev_wih, ev_whh;
    if (!inited) {
        cudaFuncSetAttribute(k_lstm, cudaFuncAttributeMaxDynamicSharedMemorySize, SM_TOTAL);
        cudaStreamCreateWithFlags(&s2, cudaStreamNonBlocking);
        cudaEventCreateWithFlags(&ev_fork, cudaEventDisableTiming);
        cudaEventCreateWithFlags(&ev_wih, cudaEventDisableTiming);
        cudaEventCreateWithFlags(&ev_whh, cudaEventDisableTiming);
        inited = 1;
    }

    // fork: side stream packs weights while main stream does graph + GAT
    cudaEventRecord(ev_fork, 0);
    cudaStreamWaitEvent(s2, ev_fork, 0);
    k_wcvt_ih<<<4096, 512, 0, s2>>>(wih);
    cudaEventRecord(ev_wih, s2);
    k_wcvt_hh<<<4096, 512, 0, s2>>>(whh);
    cudaEventRecord(ev_whh, s2);

    // main stream: CSR build + GAT
    k_graph<<<1, 512>>>(ei, gw, as_, ad_);
    k_gat_b0<<<Tt, Nn>>>(x, gw, gb);
    k_gat_rest<<<1792, 256>>>(x, gw, gb);

    // zxt needs packed w_ih
    cudaStreamWaitEvent(0, ev_wih, 0);
    {
        dim3 grid(4, 64);
        k_zxt<<<grid, 512>>>(bih, bhh);
    }

    // lstm needs packed w_hh
    cudaStreamWaitEvent(0, ev_whh, 0);
    k_lstm<<<128, 512, SM_TOTAL>>>(wlin, blin, (float*)d_out);
}